// round 1
// baseline (speedup 1.0000x reference)
#include <cuda_runtime.h>
#include <math.h>

// Problem constants
#define NNODES   50000
#define CDIM     128
#define MDIM     9        // (LMAX+1)^2
#define NB       8        // nodes per block
#define THREADS  256
#define WPITCH   132      // smem pitch for transposed W (conflict-free f4 reads)

// w3j coefficient storage (computed on device; alpha folded in)
// layout: [0..24]  (2,2,0) idx i*5+j
//         [25..69] (1,2,1) idx (i*5+j)*3+k
//         [70..114](1,1,2) idx (i*3+j)*5+k
__device__ float g_w3j[128];

// ---------------------------------------------------------------------------
// Wigner-3j init (exact, double precision, one thread — runs in ~us)
// ---------------------------------------------------------------------------
struct C2 { double r, i; };
__device__ __forceinline__ C2 cmul(C2 a, C2 b) { return { a.r*b.r - a.i*b.i, a.r*b.i + a.i*b.r }; }
__device__ __forceinline__ C2 cconj(C2 a) { return { a.r, -a.i }; }

__device__ double dfact(int n) { double r = 1.0; for (int i = 2; i <= n; ++i) r *= (double)i; return r; }

__device__ double su2cg(int j1, int m1, int j2, int m2, int j3, int m3) {
    if (m3 != m1 + m2) return 0.0;
    int vmin = -j1 + j2 + m3; if (-j1 + m1 > vmin) vmin = -j1 + m1; if (0 > vmin) vmin = 0;
    int vmax = j2 + j3 + m1; if (j3 - j1 + j2 < vmax) vmax = j3 - j1 + j2; if (j3 + m3 < vmax) vmax = j3 + m3;
    double pref = sqrt((double)(2*j3+1) * dfact(j3+j1-j2) * dfact(j3-j1+j2) * dfact(j1+j2-j3)
                       / dfact(j1+j2+j3+1)
                       * dfact(j3+m3) * dfact(j3-m3)
                       / (dfact(j1-m1) * dfact(j1+m1) * dfact(j2-m2) * dfact(j2+m2)));
    double s = 0.0;
    for (int v = vmin; v <= vmax; ++v) {
        double sign = ((v + j2 + m2) & 1) ? -1.0 : 1.0;
        s += sign / dfact(v) * dfact(j2+j3+m1-v) * dfact(j1-m1+v)
             / (dfact(j3-j1+j2-v) * dfact(j3+m3-v) * dfact(v+j1-j2-m3));
    }
    return pref * s;
}

__device__ void qmat(int l, C2 Q[5][5]) {
    for (int a = 0; a < 5; ++a) for (int b = 0; b < 5; ++b) Q[a][b] = {0.0, 0.0};
    const double is2 = 0.7071067811865475244;
    for (int m = -l; m < 0; ++m) {
        Q[l+m][l-m] = { is2, 0.0 };
        Q[l+m][l+m] = { 0.0, -is2 };
    }
    Q[l][l] = { 1.0, 0.0 };
    for (int m = 1; m <= l; ++m) {
        double s = (m & 1) ? -1.0 : 1.0;
        Q[l+m][l+m] = { s * is2, 0.0 };
        Q[l+m][l-m] = { 0.0, s * is2 };
    }
    // multiply by (-i)^l
    C2 f = (l == 0) ? C2{1.0, 0.0} : (l == 1) ? C2{0.0, -1.0} : C2{-1.0, 0.0};
    for (int a = 0; a < 2*l+1; ++a) for (int b = 0; b < 2*l+1; ++b) Q[a][b] = cmul(Q[a][b], f);
}

__device__ void compute_w3j_block(int l1, int l2, int lo, double alpha, float* out) {
    int d1 = 2*l1+1, d2 = 2*l2+1, d3 = 2*lo+1;
    C2 Q1[5][5], Q2[5][5], Q3[5][5];
    qmat(l1, Q1); qmat(l2, Q2); qmat(lo, Q3);
    double cgv[5][5][5];
    for (int i = 0; i < d1; ++i)
        for (int k = 0; k < d2; ++k)
            for (int n = 0; n < d3; ++n)
                cgv[i][k][n] = su2cg(l1, i - l1, l2, k - l2, lo, n - lo);
    double Cr[5][5][5];
    double frob2 = 0.0;
    for (int a = 0; a < d1; ++a)
        for (int b = 0; b < d2; ++b)
            for (int c = 0; c < d3; ++c) {
                C2 s = {0.0, 0.0};
                for (int i = 0; i < d1; ++i)
                    for (int k = 0; k < d2; ++k)
                        for (int n = 0; n < d3; ++n) {
                            double cg = cgv[i][k][n];
                            if (cg == 0.0) continue;
                            C2 t = cmul(cmul(Q1[i][a], Q2[k][b]), cconj(Q3[n][c]));
                            s.r += t.r * cg; s.i += t.i * cg;
                        }
                Cr[a][b][c] = s.r;
                frob2 += s.r * s.r;
            }
    double inv = alpha / sqrt(frob2);
    for (int a = 0; a < d1; ++a)
        for (int b = 0; b < d2; ++b)
            for (int c = 0; c < d3; ++c)
                out[(a*d2 + b)*d3 + c] = (float)(Cr[a][b][c] * inv);
}

__global__ void w3j_init_kernel() {
    if (threadIdx.x == 0 && blockIdx.x == 0) {
        compute_w3j_block(2, 2, 0, 1.0,                    g_w3j + 0);   // alpha = sqrt(1)
        compute_w3j_block(1, 2, 1, 1.7320508075688772935,  g_w3j + 25);  // sqrt(3)
        compute_w3j_block(1, 1, 2, 2.2360679774997896964,  g_w3j + 70);  // sqrt(5)
        for (int i = 115; i < 128; ++i) g_w3j[i] = 0.0f;
    }
}

// ---------------------------------------------------------------------------
// Fused main kernel
// ---------------------------------------------------------------------------
// smem: xs[NB*9*128] | xl[NB*9*128] | xr[NB*9*128] | wsmT[128*WPITCH] | w3s[128]
#define XS_F    (NB * MDIM * CDIM)     // 9216 floats
#define WSM_F   (CDIM * WPITCH)        // 16896 floats
#define SMEM_FLOATS (3 * XS_F + WSM_F + 128)
#define SMEM_BYTES  (SMEM_FLOATS * 4)

// One per-l block-diagonal linear: dst[(n*9+m)*128 + c] = W[l][c][:] . src row (+ bias at l=0)
__device__ __forceinline__ void linear_stage(
    const float* __restrict__ src,   // smem, NB*9*128
    float*       __restrict__ dst,   // smem (same layout) or gmem (pre-offset to block base)
    const float* __restrict__ Wg,    // [3][128][128]
    const float* __restrict__ bg,    // [128]
    float*       __restrict__ wsm,
    int tid, int warp, int lane)
{
    for (int l = 0; l < 3; ++l) {
        __syncthreads();   // previous wsm consumers done
        const float* W = Wg + l * CDIM * CDIM;
        for (int i = tid; i < CDIM * CDIM; i += THREADS) {
            int cout = i >> 7, k = i & 127;
            wsm[k * WPITCH + cout] = W[i];
        }
        __syncthreads();
        int mstart = l * l;
        int items = (2 * l + 1) * 2;   // (m, node-group-of-4)
        float4 bias = make_float4(0.f, 0.f, 0.f, 0.f);
        if (l == 0) bias = *(const float4*)&bg[lane * 4];
        for (int it = warp; it < items; it += (THREADS / 32)) {
            int m  = mstart + (it >> 1);
            int n0 = (it & 1) * 4;
            float acc[4][4];
            #pragma unroll
            for (int v = 0; v < 4; ++v) {
                acc[0][v] = bias.x; acc[1][v] = bias.y;
                acc[2][v] = bias.z; acc[3][v] = bias.w;
            }
            const float* s0 = src + ((n0 + 0) * MDIM + m) * CDIM;
            const float* s1 = src + ((n0 + 1) * MDIM + m) * CDIM;
            const float* s2 = src + ((n0 + 2) * MDIM + m) * CDIM;
            const float* s3 = src + ((n0 + 3) * MDIM + m) * CDIM;
            const float* wp = wsm + lane * 4;
            #pragma unroll 4
            for (int k = 0; k < CDIM; ++k) {
                float4 w = *(const float4*)&wp[k * WPITCH];
                float x0 = s0[k], x1 = s1[k], x2 = s2[k], x3 = s3[k];
                acc[0][0] += w.x * x0; acc[1][0] += w.y * x0; acc[2][0] += w.z * x0; acc[3][0] += w.w * x0;
                acc[0][1] += w.x * x1; acc[1][1] += w.y * x1; acc[2][1] += w.z * x1; acc[3][1] += w.w * x1;
                acc[0][2] += w.x * x2; acc[1][2] += w.y * x2; acc[2][2] += w.z * x2; acc[3][2] += w.w * x2;
                acc[0][3] += w.x * x3; acc[1][3] += w.y * x3; acc[2][3] += w.z * x3; acc[3][3] += w.w * x3;
            }
            #pragma unroll
            for (int v = 0; v < 4; ++v) {
                float4 r = make_float4(acc[0][v], acc[1][v], acc[2][v], acc[3][v]);
                *(float4*)&dst[((n0 + v) * MDIM + m) * CDIM + lane * 4] = r;
            }
        }
    }
}

__global__ __launch_bounds__(THREADS, 1)
void fused_equivariant_kernel(
    const float* __restrict__ x,
    const float* __restrict__ Wl, const float* __restrict__ bl,
    const float* __restrict__ Wr, const float* __restrict__ br,
    const float* __restrict__ Wf, const float* __restrict__ bf,
    float* __restrict__ out)
{
    extern __shared__ float smem[];
    float* xs  = smem;
    float* xlb = xs  + XS_F;
    float* xrb = xlb + XS_F;
    float* wsm = xrb + XS_F;
    float* w3s = wsm + WSM_F;

    const int tid  = threadIdx.x;
    const int warp = tid >> 5;
    const int lane = tid & 31;

    // stage inputs
    const float* xg = x + (size_t)blockIdx.x * XS_F;
    for (int i = tid; i < XS_F / 4; i += THREADS)
        ((float4*)xs)[i] = ((const float4*)xg)[i];
    if (tid < 128) w3s[tid] = g_w3j[tid];
    // (first __syncthreads inside linear_stage covers these)

    // left / right linears (smem -> smem)
    linear_stage(xs, xlb, Wl, bl, wsm, tid, warp, lane);
    linear_stage(xs, xrb, Wr, br, wsm, tid, warp, lane);
    __syncthreads();

    // channel-wise CG tensor product: (xl, xr) -> xs (overwrite input buffer)
    for (int p = tid; p < NB * CDIM; p += THREADS) {
        int node = p >> 7;
        int c    = p & 127;
        const float* A = xlb + node * MDIM * CDIM + c;
        const float* B = xrb + node * MDIM * CDIM + c;
        float a1[3], b1[3], a2[5], b2[5];
        #pragma unroll
        for (int i = 0; i < 3; ++i) { a1[i] = A[(1 + i) * CDIM]; b1[i] = B[(1 + i) * CDIM]; }
        #pragma unroll
        for (int i = 0; i < 5; ++i) { a2[i] = A[(4 + i) * CDIM]; b2[i] = B[(4 + i) * CDIM]; }

        // (2,2,0) -> l_out = 0
        float o0 = 0.f;
        #pragma unroll
        for (int i = 0; i < 5; ++i)
            #pragma unroll
            for (int j = 0; j < 5; ++j)
                o0 += w3s[i * 5 + j] * a2[i] * b2[j];

        // (1,2,1) -> l_out = 1
        float o1[3] = {0.f, 0.f, 0.f};
        #pragma unroll
        for (int i = 0; i < 3; ++i)
            #pragma unroll
            for (int j = 0; j < 5; ++j) {
                float ab = a1[i] * b2[j];
                #pragma unroll
                for (int k = 0; k < 3; ++k)
                    o1[k] += w3s[25 + (i * 5 + j) * 3 + k] * ab;
            }

        // (1,1,2) -> l_out = 2
        float o2[5] = {0.f, 0.f, 0.f, 0.f, 0.f};
        #pragma unroll
        for (int i = 0; i < 3; ++i)
            #pragma unroll
            for (int j = 0; j < 3; ++j) {
                float ab = a1[i] * b1[j];
                #pragma unroll
                for (int k = 0; k < 5; ++k)
                    o2[k] += w3s[70 + (i * 3 + j) * 5 + k] * ab;
            }

        float* O = xs + node * MDIM * CDIM + c;
        O[0] = o0;
        #pragma unroll
        for (int k = 0; k < 3; ++k) O[(1 + k) * CDIM] = o1[k];
        #pragma unroll
        for (int k = 0; k < 5; ++k) O[(4 + k) * CDIM] = o2[k];
    }

    // final linear: smem -> gmem (leading sync inside covers TP completion)
    float* outg = out + (size_t)blockIdx.x * XS_F;
    linear_stage(xs, outg, Wf, bf, wsm, tid, warp, lane);
}

// ---------------------------------------------------------------------------
extern "C" void kernel_launch(void* const* d_in, const int* in_sizes, int n_in,
                              void* d_out, int out_size) {
    const float* x  = (const float*)d_in[0];
    const float* Wl = (const float*)d_in[1];
    const float* bl = (const float*)d_in[2];
    const float* Wr = (const float*)d_in[3];
    const float* br = (const float*)d_in[4];
    const float* Wf = (const float*)d_in[5];
    const float* bf = (const float*)d_in[6];
    float* out = (float*)d_out;

    cudaFuncSetAttribute(fused_equivariant_kernel,
                         cudaFuncAttributeMaxDynamicSharedMemorySize, SMEM_BYTES);

    w3j_init_kernel<<<1, 1>>>();

    int nblocks = (NNODES + NB - 1) / NB;   // 6250
    fused_equivariant_kernel<<<nblocks, THREADS, SMEM_BYTES>>>(
        x, Wl, bl, Wr, br, Wf, bf, out);
}

// round 2
// speedup vs baseline: 1.5273x; 1.5273x over previous
#include <cuda_runtime.h>
#include <math.h>

// Problem constants
#define NNODES   50000
#define CDIM     128
#define MDIM     9
#define TILE_R   64
#define APITCH   129      // odd*? 129 % 32 = 1 -> conflict-free scalar A reads
#define WPITCH   132      // 132 % 32 = 4, float4 reads: 4 distinct 16B chunks + broadcast -> ok
#define GTHREADS 256

typedef unsigned long long ull;

// ---------------------------------------------------------------------------
// Device scratch (static __device__ globals: the sanctioned scratch path)
// ---------------------------------------------------------------------------
__device__ float g_w3j[128];
__device__ float g_wT[9 * CDIM * CDIM];             // [(which*3+l)][k][cout]
__device__ float g_xl[(size_t)NNODES * MDIM * CDIM]; // 230.4 MB
__device__ float g_xr[(size_t)NNODES * MDIM * CDIM]; // 230.4 MB

// ---------------------------------------------------------------------------
// f32x2 packed math helpers (FFMA2 path — 2 MACs per lane-slot)
// ---------------------------------------------------------------------------
__device__ __forceinline__ ull pack2(float x, float y) {
    ull r; asm("mov.b64 %0, {%1, %2};" : "=l"(r) : "f"(x), "f"(y)); return r;
}
__device__ __forceinline__ void unpack2(ull v, float& x, float& y) {
    asm("mov.b64 {%0, %1}, %2;" : "=f"(x), "=f"(y) : "l"(v));
}
__device__ __forceinline__ void ffma2(ull& d, ull a, ull b) {
    asm("fma.rn.f32x2 %0, %1, %2, %0;" : "+l"(d) : "l"(a), "l"(b));
}

// ---------------------------------------------------------------------------
// Wigner-3j init (exact, double precision, one thread)
// ---------------------------------------------------------------------------
struct C2 { double r, i; };
__device__ __forceinline__ C2 cmul(C2 a, C2 b) { return { a.r*b.r - a.i*b.i, a.r*b.i + a.i*b.r }; }
__device__ __forceinline__ C2 cconj(C2 a) { return { a.r, -a.i }; }
__device__ double dfact(int n) { double r = 1.0; for (int i = 2; i <= n; ++i) r *= (double)i; return r; }

__device__ double su2cg(int j1, int m1, int j2, int m2, int j3, int m3) {
    if (m3 != m1 + m2) return 0.0;
    int vmin = -j1 + j2 + m3; if (-j1 + m1 > vmin) vmin = -j1 + m1; if (0 > vmin) vmin = 0;
    int vmax = j2 + j3 + m1; if (j3 - j1 + j2 < vmax) vmax = j3 - j1 + j2; if (j3 + m3 < vmax) vmax = j3 + m3;
    double pref = sqrt((double)(2*j3+1) * dfact(j3+j1-j2) * dfact(j3-j1+j2) * dfact(j1+j2-j3)
                       / dfact(j1+j2+j3+1)
                       * dfact(j3+m3) * dfact(j3-m3)
                       / (dfact(j1-m1) * dfact(j1+m1) * dfact(j2-m2) * dfact(j2+m2)));
    double s = 0.0;
    for (int v = vmin; v <= vmax; ++v) {
        double sign = ((v + j2 + m2) & 1) ? -1.0 : 1.0;
        s += sign / dfact(v) * dfact(j2+j3+m1-v) * dfact(j1-m1+v)
             / (dfact(j3-j1+j2-v) * dfact(j3+m3-v) * dfact(v+j1-j2-m3));
    }
    return pref * s;
}

__device__ void qmat(int l, C2 Q[5][5]) {
    for (int a = 0; a < 5; ++a) for (int b = 0; b < 5; ++b) Q[a][b] = {0.0, 0.0};
    const double is2 = 0.7071067811865475244;
    for (int m = -l; m < 0; ++m) {
        Q[l+m][l-m] = { is2, 0.0 };
        Q[l+m][l+m] = { 0.0, -is2 };
    }
    Q[l][l] = { 1.0, 0.0 };
    for (int m = 1; m <= l; ++m) {
        double s = (m & 1) ? -1.0 : 1.0;
        Q[l+m][l+m] = { s * is2, 0.0 };
        Q[l+m][l-m] = { 0.0, s * is2 };
    }
    C2 f = (l == 0) ? C2{1.0, 0.0} : (l == 1) ? C2{0.0, -1.0} : C2{-1.0, 0.0};
    for (int a = 0; a < 2*l+1; ++a) for (int b = 0; b < 2*l+1; ++b) Q[a][b] = cmul(Q[a][b], f);
}

__device__ void compute_w3j_block(int l1, int l2, int lo, double alpha, float* out) {
    int d1 = 2*l1+1, d2 = 2*l2+1, d3 = 2*lo+1;
    C2 Q1[5][5], Q2[5][5], Q3[5][5];
    qmat(l1, Q1); qmat(l2, Q2); qmat(lo, Q3);
    double cgv[5][5][5];
    for (int i = 0; i < d1; ++i)
        for (int k = 0; k < d2; ++k)
            for (int n = 0; n < d3; ++n)
                cgv[i][k][n] = su2cg(l1, i - l1, l2, k - l2, lo, n - lo);
    double Cr[5][5][5];
    double frob2 = 0.0;
    for (int a = 0; a < d1; ++a)
        for (int b = 0; b < d2; ++b)
            for (int c = 0; c < d3; ++c) {
                C2 s = {0.0, 0.0};
                for (int i = 0; i < d1; ++i)
                    for (int k = 0; k < d2; ++k)
                        for (int n = 0; n < d3; ++n) {
                            double cg = cgv[i][k][n];
                            if (cg == 0.0) continue;
                            C2 t = cmul(cmul(Q1[i][a], Q2[k][b]), cconj(Q3[n][c]));
                            s.r += t.r * cg; s.i += t.i * cg;
                        }
                Cr[a][b][c] = s.r;
                frob2 += s.r * s.r;
            }
    double inv = alpha / sqrt(frob2);
    for (int a = 0; a < d1; ++a)
        for (int b = 0; b < d2; ++b)
            for (int c = 0; c < d3; ++c)
                out[(a*d2 + b)*d3 + c] = (float)(Cr[a][b][c] * inv);
}

__global__ void w3j_init_kernel() {
    if (threadIdx.x == 0 && blockIdx.x == 0) {
        compute_w3j_block(2, 2, 0, 1.0,                   g_w3j + 0);
        compute_w3j_block(1, 2, 1, 1.7320508075688772935, g_w3j + 25);
        compute_w3j_block(1, 1, 2, 2.2360679774997896964, g_w3j + 70);
        for (int i = 115; i < 128; ++i) g_w3j[i] = 0.0f;
    }
}

// ---------------------------------------------------------------------------
// Weight transpose prep: g_wT[b][k][cout] = W_b[cout][k], b = which*3 + l
// ---------------------------------------------------------------------------
__global__ void transpose_w_kernel(const float* __restrict__ Wl,
                                   const float* __restrict__ Wr,
                                   const float* __restrict__ Wf) {
    int b = blockIdx.x;
    int which = b / 3, l = b % 3;
    const float* W = (which == 0 ? Wl : which == 1 ? Wr : Wf) + l * CDIM * CDIM;
    float* dst = g_wT + b * CDIM * CDIM;
    for (int i = threadIdx.x; i < CDIM * CDIM; i += blockDim.x) {
        int cout = i >> 7, k = i & 127;
        dst[k * CDIM + cout] = W[i];
    }
}

// ---------------------------------------------------------------------------
// Tiled GEMM: dst[(n*9+m)*128 + cout] = sum_k W[l(m)][cout][k] * src[(n*9+m)*128+k]
// CTA tile: 64 rows (nodes, fixed m) x 128 couts. FFMA2 inner loop.
// smem: As[64][129] + Ws[128][132] = 100,608 B -> 2 CTAs/SM
// ---------------------------------------------------------------------------
#define GSMEM_FLOATS (TILE_R * APITCH + CDIM * WPITCH)
#define GSMEM_BYTES  (GSMEM_FLOATS * 4)

__global__ __launch_bounds__(GTHREADS, 2)
void gemm_kernel(const float* __restrict__ src, int wtbase,
                 const float* __restrict__ bias, float* __restrict__ dst)
{
    extern __shared__ float sm[];
    float* As = sm;                      // [row][k] pitch APITCH
    float* Ws = sm + TILE_R * APITCH;    // [k][cout] pitch WPITCH

    const int m = blockIdx.y;
    const int l = (m >= 4) ? 2 : (m >= 1) ? 1 : 0;
    const int n0 = blockIdx.x * TILE_R;
    const float* wT = g_wT + (size_t)(wtbase + l) * CDIM * CDIM;

    // Stage A (rows may be partial at the tail)
    for (int idx = threadIdx.x; idx < TILE_R * 32; idx += GTHREADS) {
        int row = idx >> 5, c4 = (idx & 31) * 4;
        int n = n0 + row;
        float4 v = make_float4(0.f, 0.f, 0.f, 0.f);
        if (n < NNODES) v = *(const float4*)&src[((size_t)n * MDIM + m) * CDIM + c4];
        float* a = &As[row * APITCH + c4];
        a[0] = v.x; a[1] = v.y; a[2] = v.z; a[3] = v.w;
    }
    // Stage W
    for (int idx = threadIdx.x; idx < CDIM * 32; idx += GTHREADS) {
        int k = idx >> 5, c4 = (idx & 31) * 4;
        *(float4*)&Ws[k * WPITCH + c4] = *(const float4*)&wT[k * CDIM + c4];
    }
    __syncthreads();

    const int warp  = threadIdx.x >> 5, lane = threadIdx.x & 31;
    const int warpR = warp & 1,  warpC = warp >> 1;
    const int laneR = lane & 7,  laneC = lane >> 3;
    const int row0  = warpR * 32 + laneR * 4;
    const int col0  = warpC * 32 + laneC * 8;

    // accumulators: 4 rows x 4 f32x2-pairs (8 couts)
    ull acc[4][4];
    if (m == 0) {
        float4 b0 = *(const float4*)&bias[col0];
        float4 b1 = *(const float4*)&bias[col0 + 4];
        ull p0 = pack2(b0.x, b0.y), p1 = pack2(b0.z, b0.w);
        ull p2 = pack2(b1.x, b1.y), p3 = pack2(b1.z, b1.w);
        #pragma unroll
        for (int r = 0; r < 4; ++r) { acc[r][0]=p0; acc[r][1]=p1; acc[r][2]=p2; acc[r][3]=p3; }
    } else {
        ull z = pack2(0.f, 0.f);
        #pragma unroll
        for (int r = 0; r < 4; ++r)
            #pragma unroll
            for (int p = 0; p < 4; ++p) acc[r][p] = z;
    }

    const float* a0 = &As[(row0 + 0) * APITCH];
    const float* a1 = &As[(row0 + 1) * APITCH];
    const float* a2 = &As[(row0 + 2) * APITCH];
    const float* a3 = &As[(row0 + 3) * APITCH];
    const float* wp = &Ws[col0];

    #pragma unroll 8
    for (int k = 0; k < CDIM; ++k) {
        // W: 8 couts = 4 packed f32x2 (reinterpret float4 as 2x u64)
        ulonglong2 wA = *(const ulonglong2*)&wp[k * WPITCH];
        ulonglong2 wB = *(const ulonglong2*)&wp[k * WPITCH + 4];
        float v0 = a0[k], v1 = a1[k], v2 = a2[k], v3 = a3[k];
        ull d0 = pack2(v0, v0), d1 = pack2(v1, v1);
        ull d2 = pack2(v2, v2), d3 = pack2(v3, v3);
        ffma2(acc[0][0], d0, wA.x); ffma2(acc[0][1], d0, wA.y);
        ffma2(acc[0][2], d0, wB.x); ffma2(acc[0][3], d0, wB.y);
        ffma2(acc[1][0], d1, wA.x); ffma2(acc[1][1], d1, wA.y);
        ffma2(acc[1][2], d1, wB.x); ffma2(acc[1][3], d1, wB.y);
        ffma2(acc[2][0], d2, wA.x); ffma2(acc[2][1], d2, wA.y);
        ffma2(acc[2][2], d2, wB.x); ffma2(acc[2][3], d2, wB.y);
        ffma2(acc[3][0], d3, wA.x); ffma2(acc[3][1], d3, wA.y);
        ffma2(acc[3][2], d3, wB.x); ffma2(acc[3][3], d3, wB.y);
    }

    // Epilogue
    #pragma unroll
    for (int r = 0; r < 4; ++r) {
        int n = n0 + row0 + r;
        if (n < NNODES) {
            float o[8];
            unpack2(acc[r][0], o[0], o[1]); unpack2(acc[r][1], o[2], o[3]);
            unpack2(acc[r][2], o[4], o[5]); unpack2(acc[r][3], o[6], o[7]);
            float* d = &dst[((size_t)n * MDIM + m) * CDIM + col0];
            *(float4*)&d[0] = make_float4(o[0], o[1], o[2], o[3]);
            *(float4*)&d[4] = make_float4(o[4], o[5], o[6], o[7]);
        }
    }
}

// ---------------------------------------------------------------------------
// Channel-wise CG tensor product: (g_xl, g_xr) -> g_xl (in place, per-thread column)
// ---------------------------------------------------------------------------
__global__ __launch_bounds__(256)
void tp_kernel() {
    __shared__ float w3s[128];
    if (threadIdx.x < 128) w3s[threadIdx.x] = g_w3j[threadIdx.x];
    __syncthreads();

    int p = blockIdx.x * 256 + threadIdx.x;
    if (p >= NNODES * CDIM) return;
    int node = p >> 7, c = p & 127;
    size_t base = (size_t)node * MDIM * CDIM + c;

    float a1[3], b1[3], a2[5], b2[5];
    #pragma unroll
    for (int i = 0; i < 3; ++i) { a1[i] = g_xl[base + (1 + i) * CDIM]; b1[i] = g_xr[base + (1 + i) * CDIM]; }
    #pragma unroll
    for (int i = 0; i < 5; ++i) { a2[i] = g_xl[base + (4 + i) * CDIM]; b2[i] = g_xr[base + (4 + i) * CDIM]; }

    // (2,2,0)
    float o0 = 0.f;
    #pragma unroll
    for (int i = 0; i < 5; ++i)
        #pragma unroll
        for (int j = 0; j < 5; ++j)
            o0 += w3s[i * 5 + j] * a2[i] * b2[j];

    // (1,2,1)
    float o1[3] = {0.f, 0.f, 0.f};
    #pragma unroll
    for (int i = 0; i < 3; ++i)
        #pragma unroll
        for (int j = 0; j < 5; ++j) {
            float ab = a1[i] * b2[j];
            #pragma unroll
            for (int k = 0; k < 3; ++k)
                o1[k] += w3s[25 + (i * 5 + j) * 3 + k] * ab;
        }

    // (1,1,2)
    float o2[5] = {0.f, 0.f, 0.f, 0.f, 0.f};
    #pragma unroll
    for (int i = 0; i < 3; ++i)
        #pragma unroll
        for (int j = 0; j < 3; ++j) {
            float ab = a1[i] * b1[j];
            #pragma unroll
            for (int k = 0; k < 5; ++k)
                o2[k] += w3s[70 + (i * 3 + j) * 5 + k] * ab;
        }

    g_xl[base] = o0;
    #pragma unroll
    for (int k = 0; k < 3; ++k) g_xl[base + (1 + k) * CDIM] = o1[k];
    #pragma unroll
    for (int k = 0; k < 5; ++k) g_xl[base + (4 + k) * CDIM] = o2[k];
}

// ---------------------------------------------------------------------------
extern "C" void kernel_launch(void* const* d_in, const int* in_sizes, int n_in,
                              void* d_out, int out_size) {
    const float* x  = (const float*)d_in[0];
    const float* Wl = (const float*)d_in[1];
    const float* bl = (const float*)d_in[2];
    const float* Wr = (const float*)d_in[3];
    const float* br = (const float*)d_in[4];
    const float* Wf = (const float*)d_in[5];
    const float* bf = (const float*)d_in[6];
    float* out = (float*)d_out;

    float *pxl = nullptr, *pxr = nullptr;
    cudaGetSymbolAddress((void**)&pxl, g_xl);
    cudaGetSymbolAddress((void**)&pxr, g_xr);

    cudaFuncSetAttribute(gemm_kernel,
                         cudaFuncAttributeMaxDynamicSharedMemorySize, GSMEM_BYTES);

    w3j_init_kernel<<<1, 1>>>();
    transpose_w_kernel<<<9, 256>>>(Wl, Wr, Wf);

    dim3 ggrid((NNODES + TILE_R - 1) / TILE_R, MDIM);   // (782, 9)
    gemm_kernel<<<ggrid, GTHREADS, GSMEM_BYTES>>>(x,   0, bl, pxl);
    gemm_kernel<<<ggrid, GTHREADS, GSMEM_BYTES>>>(x,   3, br, pxr);

    tp_kernel<<<(NNODES * CDIM + 255) / 256, 256>>>();

    gemm_kernel<<<ggrid, GTHREADS, GSMEM_BYTES>>>(pxl, 6, bf, out);
}

// round 4
// speedup vs baseline: 1.7614x; 1.1533x over previous
#include <cuda_runtime.h>
#include <cuda_bf16.h>
#include <cstdint>

// Problem constants
#define NNODES  50000
#define CDIM    128
#define MDIM    9
#define TILE_M  128
#define NTILES  ((NNODES + TILE_M - 1) / TILE_M)   // 391
#define PITCH   136                                 // bf16 pitch; 272B rows -> conflict-free frags
#define IMG_B   (TILE_M * PITCH * 2)                // 34816 bytes per 128x128 bf16 image
#define WSET_B  (2 * IMG_B)                         // hi+lo per weight set

// ---------------------------------------------------------------------------
// Device scratch
// ---------------------------------------------------------------------------
__device__ float g_w3j[128];
__device__ __align__(16) char g_wimg[9 * WSET_B];    // [b][hi|lo][cout][PITCH] bf16
__device__ float g_xl[(size_t)NNODES * MDIM * CDIM];
__device__ float g_xr[(size_t)NNODES * MDIM * CDIM];

// ---------------------------------------------------------------------------
// HMMA helper: m16n8k16 row.col f32 += bf16 x bf16
// ---------------------------------------------------------------------------
__device__ __forceinline__ void mma_bf16(float* d, const uint32_t* a, uint32_t b0, uint32_t b1) {
    asm volatile(
        "mma.sync.aligned.m16n8k16.row.col.f32.bf16.bf16.f32 "
        "{%0,%1,%2,%3}, {%4,%5,%6,%7}, {%8,%9}, {%0,%1,%2,%3};"
        : "+f"(d[0]), "+f"(d[1]), "+f"(d[2]), "+f"(d[3])
        : "r"(a[0]), "r"(a[1]), "r"(a[2]), "r"(a[3]), "r"(b0), "r"(b1));
}

// ---------------------------------------------------------------------------
// Wigner-3j init (exact, double precision, one thread)
// ---------------------------------------------------------------------------
struct C2 { double r, i; };
__device__ __forceinline__ C2 cmul(C2 a, C2 b) { return { a.r*b.r - a.i*b.i, a.r*b.i + a.i*b.r }; }
__device__ __forceinline__ C2 cconj(C2 a) { return { a.r, -a.i }; }
__device__ double dfact(int n) { double r = 1.0; for (int i = 2; i <= n; ++i) r *= (double)i; return r; }

__device__ double su2cg(int j1, int m1, int j2, int m2, int j3, int m3) {
    if (m3 != m1 + m2) return 0.0;
    int vmin = -j1 + j2 + m3; if (-j1 + m1 > vmin) vmin = -j1 + m1; if (0 > vmin) vmin = 0;
    int vmax = j2 + j3 + m1; if (j3 - j1 + j2 < vmax) vmax = j3 - j1 + j2; if (j3 + m3 < vmax) vmax = j3 + m3;
    double pref = sqrt((double)(2*j3+1) * dfact(j3+j1-j2) * dfact(j3-j1+j2) * dfact(j1+j2-j3)
                       / dfact(j1+j2+j3+1)
                       * dfact(j3+m3) * dfact(j3-m3)
                       / (dfact(j1-m1) * dfact(j1+m1) * dfact(j2-m2) * dfact(j2+m2)));
    double s = 0.0;
    for (int v = vmin; v <= vmax; ++v) {
        double sign = ((v + j2 + m2) & 1) ? -1.0 : 1.0;
        s += sign / dfact(v) * dfact(j2+j3+m1-v) * dfact(j1-m1+v)
             / (dfact(j3-j1+j2-v) * dfact(j3+m3-v) * dfact(v+j1-j2-m3));
    }
    return pref * s;
}

__device__ void qmat(int l, C2 Q[5][5]) {
    for (int a = 0; a < 5; ++a) for (int b = 0; b < 5; ++b) Q[a][b] = {0.0, 0.0};
    const double is2 = 0.7071067811865475244;
    for (int m = -l; m < 0; ++m) {
        Q[l+m][l-m] = { is2, 0.0 };
        Q[l+m][l+m] = { 0.0, -is2 };
    }
    Q[l][l] = { 1.0, 0.0 };
    for (int m = 1; m <= l; ++m) {
        double s = (m & 1) ? -1.0 : 1.0;
        Q[l+m][l+m] = { s * is2, 0.0 };
        Q[l+m][l-m] = { 0.0, s * is2 };
    }
    C2 f = (l == 0) ? C2{1.0, 0.0} : (l == 1) ? C2{0.0, -1.0} : C2{-1.0, 0.0};
    for (int a = 0; a < 2*l+1; ++a) for (int b = 0; b < 2*l+1; ++b) Q[a][b] = cmul(Q[a][b], f);
}

__device__ void compute_w3j_block(int l1, int l2, int lo, double alpha, float* out) {
    int d1 = 2*l1+1, d2 = 2*l2+1, d3 = 2*lo+1;
    C2 Q1[5][5], Q2[5][5], Q3[5][5];
    qmat(l1, Q1); qmat(l2, Q2); qmat(lo, Q3);
    double cgv[5][5][5];
    for (int i = 0; i < d1; ++i)
        for (int k = 0; k < d2; ++k)
            for (int n = 0; n < d3; ++n)
                cgv[i][k][n] = su2cg(l1, i - l1, l2, k - l2, lo, n - lo);
    double Cr[5][5][5];
    double frob2 = 0.0;
    for (int a = 0; a < d1; ++a)
        for (int b = 0; b < d2; ++b)
            for (int c = 0; c < d3; ++c) {
                C2 s = {0.0, 0.0};
                for (int i = 0; i < d1; ++i)
                    for (int k = 0; k < d2; ++k)
                        for (int n = 0; n < d3; ++n) {
                            double cg = cgv[i][k][n];
                            if (cg == 0.0) continue;
                            C2 t = cmul(cmul(Q1[i][a], Q2[k][b]), cconj(Q3[n][c]));
                            s.r += t.r * cg; s.i += t.i * cg;
                        }
                Cr[a][b][c] = s.r;
                frob2 += s.r * s.r;
            }
    double inv = alpha / sqrt(frob2);
    for (int a = 0; a < d1; ++a)
        for (int b = 0; b < d2; ++b)
            for (int c = 0; c < d3; ++c)
                out[(a*d2 + b)*d3 + c] = (float)(Cr[a][b][c] * inv);
}

__global__ void w3j_init_kernel() {
    if (threadIdx.x == 0 && blockIdx.x == 0) {
        compute_w3j_block(2, 2, 0, 1.0,                   g_w3j + 0);
        compute_w3j_block(1, 2, 1, 1.7320508075688772935, g_w3j + 25);
        compute_w3j_block(1, 1, 2, 2.2360679774997896964, g_w3j + 70);
        for (int i = 115; i < 128; ++i) g_w3j[i] = 0.0f;
    }
}

// ---------------------------------------------------------------------------
// Weight prep: split fp32 W into bf16 hi/lo images [cout][k], pitch PITCH.
// b = which*3 + l.
// ---------------------------------------------------------------------------
__global__ void wsplit_kernel(const float* __restrict__ Wl,
                              const float* __restrict__ Wr,
                              const float* __restrict__ Wf) {
    int b = blockIdx.x;
    int which = b / 3, ll = b % 3;
    const float* W = (which == 0 ? Wl : which == 1 ? Wr : Wf) + ll * CDIM * CDIM;
    char* hi = g_wimg + (size_t)b * WSET_B;
    char* lo = hi + IMG_B;
    for (int i = threadIdx.x; i < CDIM * CDIM; i += blockDim.x) {
        int cout = i >> 7, k = i & 127;
        float x = W[i];
        __nv_bfloat16 h = __float2bfloat16(x);
        __nv_bfloat16 lw = __float2bfloat16(x - __bfloat162float(h));
        int o = (cout * PITCH + k) * 2;
        *(__nv_bfloat16*)(hi + o) = h;
        *(__nv_bfloat16*)(lo + o) = lw;
    }
}

// ---------------------------------------------------------------------------
// HMMA GEMM stage kernel.
// CTA: 128 nodes (fixed m) x 128 couts, K=128, bf16 hi/lo 3-pass split.
// nout==2: two weight sets from one staged A (left+right fused).
// smem: A_hi | A_lo | Wset0(hi|lo) [| Wset1(hi|lo)]
// ---------------------------------------------------------------------------
__global__ __launch_bounds__(256, 1)
void mma_gemm_kernel(const float* __restrict__ src,
                     int wb0, int wb1, int nout,
                     const float* __restrict__ bias0,
                     const float* __restrict__ bias1,
                     float* __restrict__ out0,
                     float* __restrict__ out1)
{
    extern __shared__ __align__(16) char smem[];
    char* A_hi = smem;
    char* A_lo = smem + IMG_B;
    char* Wsm  = smem + 2 * IMG_B;

    const int tid = threadIdx.x, wid = tid >> 5, lane = tid & 31;
    const int g = lane >> 2, t = lane & 3;
    const int m = blockIdx.y;
    const int l = (m >= 4) ? 2 : (m >= 1) ? 1 : 0;
    const int n0 = blockIdx.x * TILE_M;
    const int warpR = wid & 3, warpC = wid >> 2;   // 4 x 2 warps

    // --- Stage A: fp32 -> bf16 hi/lo images ---
    for (int idx = tid; idx < TILE_M * 32; idx += 256) {
        int row = idx >> 5, c4 = (idx & 31) << 2;
        int n = n0 + row;
        float4 v = make_float4(0.f, 0.f, 0.f, 0.f);
        if (n < NNODES) v = *(const float4*)&src[((size_t)n * MDIM + m) * CDIM + c4];
        __nv_bfloat162 h01 = __floats2bfloat162_rn(v.x, v.y);
        __nv_bfloat162 h23 = __floats2bfloat162_rn(v.z, v.w);
        __nv_bfloat162 l01 = __floats2bfloat162_rn(v.x - __bfloat162float(h01.x),
                                                   v.y - __bfloat162float(h01.y));
        __nv_bfloat162 l23 = __floats2bfloat162_rn(v.z - __bfloat162float(h23.x),
                                                   v.w - __bfloat162float(h23.y));
        int o = (row * PITCH + c4) * 2;
        *(uint2*)(A_hi + o) = make_uint2(*(uint32_t*)&h01, *(uint32_t*)&h23);
        *(uint2*)(A_lo + o) = make_uint2(*(uint32_t*)&l01, *(uint32_t*)&l23);
    }

    // --- Stage W: straight float4 copy of pre-split images ---
    {
        const float4* s0 = (const float4*)(g_wimg + (size_t)(wb0 + l) * WSET_B);
        float4* d0 = (float4*)Wsm;
        for (int i = tid; i < WSET_B / 16; i += 256) d0[i] = s0[i];
        if (nout == 2) {
            const float4* s1 = (const float4*)(g_wimg + (size_t)(wb1 + l) * WSET_B);
            float4* d1 = (float4*)(Wsm + WSET_B);
            for (int i = tid; i < WSET_B / 16; i += 256) d1[i] = s1[i];
        }
    }
    __syncthreads();

    for (int which = 0; which < nout; ++which) {
        const char* Wset = Wsm + which * WSET_B;
        const char* Apass[3] = { A_hi, A_hi, A_lo };
        const char* Wpass[3] = { Wset, Wset + IMG_B, Wset };
        const float* bias = which ? bias1 : bias0;
        float* out = which ? out1 : out0;

        // accumulators: 2 row frags x 8 col frags x 4
        float acc[2][8][4];
        if (m == 0) {
            #pragma unroll
            for (int cf = 0; cf < 8; ++cf) {
                int cb = warpC * 64 + cf * 8 + 2 * t;
                float2 bv = *(const float2*)&bias[cb];
                #pragma unroll
                for (int mf = 0; mf < 2; ++mf) {
                    acc[mf][cf][0] = bv.x; acc[mf][cf][1] = bv.y;
                    acc[mf][cf][2] = bv.x; acc[mf][cf][3] = bv.y;
                }
            }
        } else {
            #pragma unroll
            for (int mf = 0; mf < 2; ++mf)
                #pragma unroll
                for (int cf = 0; cf < 8; ++cf)
                    #pragma unroll
                    for (int q = 0; q < 4; ++q) acc[mf][cf][q] = 0.f;
        }

        #pragma unroll
        for (int pass = 0; pass < 3; ++pass) {
            const char* Ap = Apass[pass];
            const char* Wp = Wpass[pass];
            #pragma unroll
            for (int ks = 0; ks < 8; ++ks) {
                int k0 = ks * 16;
                uint32_t a[2][4];
                #pragma unroll
                for (int mf = 0; mf < 2; ++mf) {
                    int r = warpR * 32 + mf * 16 + g;
                    const char* base = Ap + (r * PITCH + k0 + 2 * t) * 2;
                    a[mf][0] = *(const uint32_t*)(base);
                    a[mf][1] = *(const uint32_t*)(base + 8 * PITCH * 2);
                    a[mf][2] = *(const uint32_t*)(base + 16);
                    a[mf][3] = *(const uint32_t*)(base + 8 * PITCH * 2 + 16);
                }
                #pragma unroll
                for (int cf = 0; cf < 8; ++cf) {
                    int n = warpC * 64 + cf * 8 + g;
                    const char* bb = Wp + (n * PITCH + k0 + 2 * t) * 2;
                    uint32_t b0 = *(const uint32_t*)bb;
                    uint32_t b1 = *(const uint32_t*)(bb + 16);
                    mma_bf16(acc[0][cf], a[0], b0, b1);
                    mma_bf16(acc[1][cf], a[1], b0, b1);
                }
            }
        }

        // --- Epilogue: scattered float2 stores (32B sectors per 4-lane group) ---
        #pragma unroll
        for (int mf = 0; mf < 2; ++mf) {
            int r0 = n0 + warpR * 32 + mf * 16 + g;
            int r1 = r0 + 8;
            #pragma unroll
            for (int cf = 0; cf < 8; ++cf) {
                int cb = warpC * 64 + cf * 8 + 2 * t;
                if (r0 < NNODES)
                    *(float2*)&out[((size_t)r0 * MDIM + m) * CDIM + cb] =
                        make_float2(acc[mf][cf][0], acc[mf][cf][1]);
                if (r1 < NNODES)
                    *(float2*)&out[((size_t)r1 * MDIM + m) * CDIM + cb] =
                        make_float2(acc[mf][cf][2], acc[mf][cf][3]);
            }
        }
    }
}

// ---------------------------------------------------------------------------
// Channel-wise CG tensor product (fp32, memory-bound): (g_xl, g_xr) -> g_xl
// ---------------------------------------------------------------------------
__global__ __launch_bounds__(256)
void tp_kernel() {
    __shared__ float w3s[128];
    if (threadIdx.x < 128) w3s[threadIdx.x] = g_w3j[threadIdx.x];
    __syncthreads();

    int p = blockIdx.x * 256 + threadIdx.x;
    if (p >= NNODES * CDIM) return;
    int node = p >> 7, c = p & 127;
    size_t base = (size_t)node * MDIM * CDIM + c;

    float a1[3], b1[3], a2[5], b2[5];
    #pragma unroll
    for (int i = 0; i < 3; ++i) { a1[i] = g_xl[base + (1 + i) * CDIM]; b1[i] = g_xr[base + (1 + i) * CDIM]; }
    #pragma unroll
    for (int i = 0; i < 5; ++i) { a2[i] = g_xl[base + (4 + i) * CDIM]; b2[i] = g_xr[base + (4 + i) * CDIM]; }

    float o0 = 0.f;
    #pragma unroll
    for (int i = 0; i < 5; ++i)
        #pragma unroll
        for (int j = 0; j < 5; ++j)
            o0 += w3s[i * 5 + j] * a2[i] * b2[j];

    float o1[3] = {0.f, 0.f, 0.f};
    #pragma unroll
    for (int i = 0; i < 3; ++i)
        #pragma unroll
        for (int j = 0; j < 5; ++j) {
            float ab = a1[i] * b2[j];
            #pragma unroll
            for (int k = 0; k < 3; ++k)
                o1[k] += w3s[25 + (i * 5 + j) * 3 + k] * ab;
        }

    float o2[5] = {0.f, 0.f, 0.f, 0.f, 0.f};
    #pragma unroll
    for (int i = 0; i < 3; ++i)
        #pragma unroll
        for (int j = 0; j < 3; ++j) {
            float ab = a1[i] * b1[j];
            #pragma unroll
            for (int k = 0; k < 5; ++k)
                o2[k] += w3s[70 + (i * 3 + j) * 5 + k] * ab;
        }

    g_xl[base] = o0;
    #pragma unroll
    for (int k = 0; k < 3; ++k) g_xl[base + (1 + k) * CDIM] = o1[k];
    #pragma unroll
    for (int k = 0; k < 5; ++k) g_xl[base + (4 + k) * CDIM] = o2[k];
}

// ---------------------------------------------------------------------------
extern "C" void kernel_launch(void* const* d_in, const int* in_sizes, int n_in,
                              void* d_out, int out_size) {
    const float* x  = (const float*)d_in[0];
    const float* Wl = (const float*)d_in[1];
    const float* bl = (const float*)d_in[2];
    const float* Wr = (const float*)d_in[3];
    const float* br = (const float*)d_in[4];
    const float* Wf = (const float*)d_in[5];
    const float* bf = (const float*)d_in[6];
    float* out = (float*)d_out;

    float *pxl = nullptr, *pxr = nullptr;
    cudaGetSymbolAddress((void**)&pxl, g_xl);
    cudaGetSymbolAddress((void**)&pxr, g_xr);

    const int LR_SMEM = 2 * IMG_B + 2 * WSET_B;  // 208896
    const int F_SMEM  = 2 * IMG_B + 1 * WSET_B;  // 139264
    cudaFuncSetAttribute(mma_gemm_kernel,
                         cudaFuncAttributeMaxDynamicSharedMemorySize, LR_SMEM);

    w3j_init_kernel<<<1, 1>>>();
    wsplit_kernel<<<9, 256>>>(Wl, Wr, Wf);

    dim3 grid(NTILES, MDIM);
    // left + right linears in one pass over x
    mma_gemm_kernel<<<grid, 256, LR_SMEM>>>(x, 0, 3, 2, bl, br, pxl, pxr);
    // CG tensor product
    tp_kernel<<<(NNODES * CDIM + 255) / 256, 256>>>();
    // final linear -> d_out
    mma_gemm_kernel<<<grid, 256, F_SMEM>>>(pxl, 6, 0, 1, bf, nullptr, out, nullptr);
}

// round 7
// speedup vs baseline: 3.4701x; 1.9701x over previous
#include <cuda_runtime.h>
#include <cuda_bf16.h>
#include <cstdint>

// Problem constants
#define NNODES  50000
#define CDIM    128
#define MDIM    9
#define TILE_M  128
#define NTILES  ((NNODES + TILE_M - 1) / TILE_M)   // 391
#define PITCH   136                                 // bf16 pitch; 272B rows -> conflict-free frags
#define IMG_B   (TILE_M * PITCH * 2)                // 34816 bytes per 128x128 bf16 image
#define WSET_B  (2 * IMG_B)                         // hi+lo per weight set

// ---------------------------------------------------------------------------
// Device scratch
// ---------------------------------------------------------------------------
__device__ float g_w3j[128];
__device__ __align__(16) char g_wimg[9 * WSET_B];    // [b][hi|lo][cout][PITCH] bf16
__device__ float g_xl[(size_t)NNODES * MDIM * CDIM];
__device__ float g_xr[(size_t)NNODES * MDIM * CDIM];

// ---------------------------------------------------------------------------
// HMMA + ldmatrix helpers
// ---------------------------------------------------------------------------
__device__ __forceinline__ void mma_bf16(float* d, const uint32_t* a, uint32_t b0, uint32_t b1) {
    asm volatile(
        "mma.sync.aligned.m16n8k16.row.col.f32.bf16.bf16.f32 "
        "{%0,%1,%2,%3}, {%4,%5,%6,%7}, {%8,%9}, {%0,%1,%2,%3};"
        : "+f"(d[0]), "+f"(d[1]), "+f"(d[2]), "+f"(d[3])
        : "r"(a[0]), "r"(a[1]), "r"(a[2]), "r"(a[3]), "r"(b0), "r"(b1));
}
__device__ __forceinline__ void ldsm_x4(uint32_t& r0, uint32_t& r1, uint32_t& r2, uint32_t& r3,
                                        uint32_t addr) {
    asm volatile("ldmatrix.sync.aligned.m8n8.x4.shared.b16 {%0,%1,%2,%3}, [%4];"
                 : "=r"(r0), "=r"(r1), "=r"(r2), "=r"(r3) : "r"(addr));
}
__device__ __forceinline__ uint32_t smem_u32(const void* p) {
    return (uint32_t)__cvta_generic_to_shared(p);
}

// ---------------------------------------------------------------------------
// Wigner-3j init — parallel: 3 blocks x 128 threads (single-thread version
// cost ~1.3ms/replay on the DFMA pipe!)
// ---------------------------------------------------------------------------
struct C2 { double r, i; };
__device__ __forceinline__ C2 cmul(C2 a, C2 b) { return { a.r*b.r - a.i*b.i, a.r*b.i + a.i*b.r }; }
__device__ double dfact(int n) { double r = 1.0; for (int i = 2; i <= n; ++i) r *= (double)i; return r; }

__device__ double su2cg(int j1, int m1, int j2, int m2, int j3, int m3) {
    if (m3 != m1 + m2) return 0.0;
    int vmin = -j1 + j2 + m3; if (-j1 + m1 > vmin) vmin = -j1 + m1; if (0 > vmin) vmin = 0;
    int vmax = j2 + j3 + m1; if (j3 - j1 + j2 < vmax) vmax = j3 - j1 + j2; if (j3 + m3 < vmax) vmax = j3 + m3;
    double pref = sqrt((double)(2*j3+1) * dfact(j3+j1-j2) * dfact(j3-j1+j2) * dfact(j1+j2-j3)
                       / dfact(j1+j2+j3+1)
                       * dfact(j3+m3) * dfact(j3-m3)
                       / (dfact(j1-m1) * dfact(j1+m1) * dfact(j2-m2) * dfact(j2+m2)));
    double s = 0.0;
    for (int v = vmin; v <= vmax; ++v) {
        double sign = ((v + j2 + m2) & 1) ? -1.0 : 1.0;
        s += sign / dfact(v) * dfact(j2+j3+m1-v) * dfact(j1-m1+v)
             / (dfact(j3-j1+j2-v) * dfact(j3+m3-v) * dfact(v+j1-j2-m3));
    }
    return pref * s;
}

__device__ void qmat(int l, C2 Q[5][5]) {
    for (int a = 0; a < 5; ++a) for (int b = 0; b < 5; ++b) Q[a][b] = {0.0, 0.0};
    const double is2 = 0.7071067811865475244;
    for (int m = -l; m < 0; ++m) {
        Q[l+m][l-m] = { is2, 0.0 };
        Q[l+m][l+m] = { 0.0, -is2 };
    }
    Q[l][l] = { 1.0, 0.0 };
    for (int m = 1; m <= l; ++m) {
        double s = (m & 1) ? -1.0 : 1.0;
        Q[l+m][l+m] = { s * is2, 0.0 };
        Q[l+m][l-m] = { 0.0, s * is2 };
    }
    C2 f = (l == 0) ? C2{1.0, 0.0} : (l == 1) ? C2{0.0, -1.0} : C2{-1.0, 0.0};
    for (int a = 0; a < 2*l+1; ++a) for (int b = 0; b < 2*l+1; ++b) Q[a][b] = cmul(Q[a][b], f);
}

__global__ void w3j_init_kernel() {
    __shared__ double cgs[125];
    __shared__ double crs[125];
    __shared__ double red[128];

    const int tid = threadIdx.x;
    const int blk = blockIdx.x;
    const int l1 = (blk == 0) ? 2 : 1;
    const int l2 = (blk == 2) ? 1 : 2;
    const int lo = blk == 0 ? 0 : (blk == 1 ? 1 : 2);
    const double alpha = (blk == 0) ? 1.0 : (blk == 1 ? 1.7320508075688772935 : 2.2360679774997896964);
    const int off = (blk == 0) ? 0 : (blk == 1 ? 25 : 70);
    const int d1 = 2*l1+1, d2 = 2*l2+1, d3 = 2*lo+1;
    const int nel = d1 * d2 * d3;

    if (tid < nel) {
        int i = tid / (d2 * d3), k = (tid / d3) % d2, n = tid % d3;
        cgs[tid] = su2cg(l1, i - l1, l2, k - l2, lo, n - lo);
    }
    __syncthreads();

    double cr = 0.0;
    if (tid < nel) {
        C2 Q1[5][5], Q2[5][5], Q3[5][5];
        qmat(l1, Q1); qmat(l2, Q2); qmat(lo, Q3);
        int a = tid / (d2 * d3), b = (tid / d3) % d2, c = tid % d3;
        C2 s = {0.0, 0.0};
        for (int i = 0; i < d1; ++i)
            for (int k = 0; k < d2; ++k) {
                C2 q12 = cmul(Q1[i][a], Q2[k][b]);
                for (int n = 0; n < d3; ++n) {
                    double cg = cgs[(i * d2 + k) * d3 + n];
                    if (cg == 0.0) continue;
                    C2 q3c = { Q3[n][c].r, -Q3[n][c].i };
                    C2 t = cmul(q12, q3c);
                    s.r += t.r * cg; s.i += t.i * cg;
                }
            }
        cr = s.r;
        crs[tid] = cr;
    }

    red[tid] = (tid < nel) ? cr * cr : 0.0;
    __syncthreads();
    for (int stride = 64; stride > 0; stride >>= 1) {
        if (tid < stride) red[tid] += red[tid + stride];
        __syncthreads();
    }
    double inv = alpha * rsqrt(red[0]);

    if (tid < nel) g_w3j[off + tid] = (float)(crs[tid] * inv);
    if (blk == 2 && tid >= 115 && tid < 128) g_w3j[tid] = 0.0f;
}

// ---------------------------------------------------------------------------
// Weight prep: split fp32 W into bf16 hi/lo images [cout][k], pitch PITCH.
// ---------------------------------------------------------------------------
__global__ void wsplit_kernel(const float* __restrict__ Wl,
                              const float* __restrict__ Wr,
                              const float* __restrict__ Wf) {
    int b = blockIdx.x;
    int which = b / 3, ll = b % 3;
    const float* W = (which == 0 ? Wl : which == 1 ? Wr : Wf) + ll * CDIM * CDIM;
    char* hi = g_wimg + (size_t)b * WSET_B;
    char* lo = hi + IMG_B;
    for (int i = threadIdx.x; i < CDIM * CDIM; i += blockDim.x) {
        int cout = i >> 7, k = i & 127;
        float x = W[i];
        __nv_bfloat16 h = __float2bfloat16(x);
        __nv_bfloat16 lw = __float2bfloat16(x - __bfloat162float(h));
        int o = (cout * PITCH + k) * 2;
        *(__nv_bfloat16*)(hi + o) = h;
        *(__nv_bfloat16*)(lo + o) = lw;
    }
}

// ---------------------------------------------------------------------------
// HMMA GEMM stage kernel (ldmatrix fragment loads).
// CTA: 128 nodes (fixed m) x 128 couts, K=128, bf16 hi/lo 3-pass split.
// ---------------------------------------------------------------------------
__global__ __launch_bounds__(256, 1)
void mma_gemm_kernel(const float* __restrict__ src,
                     int wb0, int wb1, int nout,
                     const float* __restrict__ bias0,
                     const float* __restrict__ bias1,
                     float* __restrict__ out0,
                     float* __restrict__ out1)
{
    extern __shared__ __align__(16) char smem[];
    char* A_hi = smem;
    char* A_lo = smem + IMG_B;
    char* Wsm  = smem + 2 * IMG_B;

    const int tid = threadIdx.x, wid = tid >> 5, lane = tid & 31;
    const int g = lane >> 2, t = lane & 3;
    const int m = blockIdx.y;
    const int l = (m >= 4) ? 2 : (m >= 1) ? 1 : 0;
    const int n0 = blockIdx.x * TILE_M;
    const int warpR = wid & 3, warpC = wid >> 2;   // 4 x 2 warps

    // --- Stage A: fp32 -> bf16 hi/lo images ---
    for (int idx = tid; idx < TILE_M * 32; idx += 256) {
        int row = idx >> 5, c4 = (idx & 31) << 2;
        int n = n0 + row;
        float4 v = make_float4(0.f, 0.f, 0.f, 0.f);
        if (n < NNODES) v = *(const float4*)&src[((size_t)n * MDIM + m) * CDIM + c4];
        __nv_bfloat162 h01 = __floats2bfloat162_rn(v.x, v.y);
        __nv_bfloat162 h23 = __floats2bfloat162_rn(v.z, v.w);
        __nv_bfloat162 l01 = __floats2bfloat162_rn(v.x - __bfloat162float(h01.x),
                                                   v.y - __bfloat162float(h01.y));
        __nv_bfloat162 l23 = __floats2bfloat162_rn(v.z - __bfloat162float(h23.x),
                                                   v.w - __bfloat162float(h23.y));
        int o = (row * PITCH + c4) * 2;
        *(uint2*)(A_hi + o) = make_uint2(*(uint32_t*)&h01, *(uint32_t*)&h23);
        *(uint2*)(A_lo + o) = make_uint2(*(uint32_t*)&l01, *(uint32_t*)&l23);
    }

    // --- Stage W: straight float4 copy of pre-split images ---
    {
        const float4* s0 = (const float4*)(g_wimg + (size_t)(wb0 + l) * WSET_B);
        float4* d0 = (float4*)Wsm;
        for (int i = tid; i < WSET_B / 16; i += 256) d0[i] = s0[i];
        if (nout == 2) {
            const float4* s1 = (const float4*)(g_wimg + (size_t)(wb1 + l) * WSET_B);
            float4* d1 = (float4*)(Wsm + WSET_B);
            for (int i = tid; i < WSET_B / 16; i += 256) d1[i] = s1[i];
        }
    }
    __syncthreads();

    // --- per-lane ldmatrix offsets (bytes) ---
    // A x4: j = lane>>3 selects matrix: m0 rows0-7/k0-7 (=a0), m1 rows8-15/k0-7 (=a1),
    //       m2 rows0-7/k8-15 (=a2), m3 rows8-15/k8-15 (=a3)
    const int jm = lane >> 3, rr = lane & 7;
    uint32_t aoff[2];
    #pragma unroll
    for (int mf = 0; mf < 2; ++mf) {
        int row = warpR * 32 + mf * 16 + ((jm & 1) << 3) + rr;
        aoff[mf] = (uint32_t)((row * PITCH + ((jm >> 1) << 3)) * 2);
    }
    // B x4 per cf-pair: m0 n0-7/k0-7 (=b0 even cf), m1 n0-7/k8-15 (=b1 even cf),
    //                   m2 n8-15/k0-7 (=b0 odd cf), m3 n8-15/k8-15 (=b1 odd cf)
    uint32_t boff[4];
    #pragma unroll
    for (int cp = 0; cp < 4; ++cp) {
        int n = warpC * 64 + cp * 16 + ((jm >> 1) << 3) + rr;
        boff[cp] = (uint32_t)((n * PITCH + ((jm & 1) << 3)) * 2);
    }

    const uint32_t uA_hi = smem_u32(A_hi), uA_lo = smem_u32(A_lo), uW = smem_u32(Wsm);

    for (int which = 0; which < nout; ++which) {
        const uint32_t uWset = uW + which * WSET_B;
        const uint32_t uApass[3] = { uA_hi, uA_hi, uA_lo };
        const uint32_t uWpass[3] = { uWset, uWset + IMG_B, uWset };
        const float* bias = which ? bias1 : bias0;
        float* out = which ? out1 : out0;

        float acc[2][8][4];
        if (m == 0) {
            #pragma unroll
            for (int cf = 0; cf < 8; ++cf) {
                int cb = warpC * 64 + cf * 8 + 2 * t;
                float2 bv = *(const float2*)&bias[cb];
                #pragma unroll
                for (int mf = 0; mf < 2; ++mf) {
                    acc[mf][cf][0] = bv.x; acc[mf][cf][1] = bv.y;
                    acc[mf][cf][2] = bv.x; acc[mf][cf][3] = bv.y;
                }
            }
        } else {
            #pragma unroll
            for (int mf = 0; mf < 2; ++mf)
                #pragma unroll
                for (int cf = 0; cf < 8; ++cf)
                    #pragma unroll
                    for (int q = 0; q < 4; ++q) acc[mf][cf][q] = 0.f;
        }

        #pragma unroll
        for (int pass = 0; pass < 3; ++pass) {
            const uint32_t uA = uApass[pass];
            const uint32_t uWp = uWpass[pass];
            #pragma unroll
            for (int ks = 0; ks < 8; ++ks) {
                const uint32_t kofs = (uint32_t)(ks * 32);   // 16 bf16 per slice
                uint32_t a[2][4];
                ldsm_x4(a[0][0], a[0][1], a[0][2], a[0][3], uA + aoff[0] + kofs);
                ldsm_x4(a[1][0], a[1][1], a[1][2], a[1][3], uA + aoff[1] + kofs);
                #pragma unroll
                for (int cp = 0; cp < 4; ++cp) {
                    uint32_t b0, b1, b2, b3;
                    ldsm_x4(b0, b1, b2, b3, uWp + boff[cp] + kofs);
                    mma_bf16(acc[0][2*cp],     a[0], b0, b1);
                    mma_bf16(acc[1][2*cp],     a[1], b0, b1);
                    mma_bf16(acc[0][2*cp + 1], a[0], b2, b3);
                    mma_bf16(acc[1][2*cp + 1], a[1], b2, b3);
                }
            }
        }

        // --- Epilogue ---
        #pragma unroll
        for (int mf = 0; mf < 2; ++mf) {
            int r0 = n0 + warpR * 32 + mf * 16 + g;
            int r1 = r0 + 8;
            #pragma unroll
            for (int cf = 0; cf < 8; ++cf) {
                int cb = warpC * 64 + cf * 8 + 2 * t;
                if (r0 < NNODES)
                    *(float2*)&out[((size_t)r0 * MDIM + m) * CDIM + cb] =
                        make_float2(acc[mf][cf][0], acc[mf][cf][1]);
                if (r1 < NNODES)
                    *(float2*)&out[((size_t)r1 * MDIM + m) * CDIM + cb] =
                        make_float2(acc[mf][cf][2], acc[mf][cf][3]);
            }
        }
    }
}

// ---------------------------------------------------------------------------
// Channel-wise CG tensor product (fp32, memory-bound): (g_xl, g_xr) -> g_xl
// ---------------------------------------------------------------------------
__global__ __launch_bounds__(256)
void tp_kernel() {
    __shared__ float w3s[128];
    if (threadIdx.x < 128) w3s[threadIdx.x] = g_w3j[threadIdx.x];
    __syncthreads();

    int p = blockIdx.x * 256 + threadIdx.x;
    if (p >= NNODES * CDIM) return;
    int node = p >> 7, c = p & 127;
    size_t base = (size_t)node * MDIM * CDIM + c;

    float a1[3], b1[3], a2[5], b2[5];
    #pragma unroll
    for (int i = 0; i < 3; ++i) { a1[i] = g_xl[base + (1 + i) * CDIM]; b1[i] = g_xr[base + (1 + i) * CDIM]; }
    #pragma unroll
    for (int i = 0; i < 5; ++i) { a2[i] = g_xl[base + (4 + i) * CDIM]; b2[i] = g_xr[base + (4 + i) * CDIM]; }

    float o0 = 0.f;
    #pragma unroll
    for (int i = 0; i < 5; ++i)
        #pragma unroll
        for (int j = 0; j < 5; ++j)
            o0 += w3s[i * 5 + j] * a2[i] * b2[j];

    float o1[3] = {0.f, 0.f, 0.f};
    #pragma unroll
    for (int i = 0; i < 3; ++i)
        #pragma unroll
        for (int j = 0; j < 5; ++j) {
            float ab = a1[i] * b2[j];
            #pragma unroll
            for (int k = 0; k < 3; ++k)
                o1[k] += w3s[25 + (i * 5 + j) * 3 + k] * ab;
        }

    float o2[5] = {0.f, 0.f, 0.f, 0.f, 0.f};
    #pragma unroll
    for (int i = 0; i < 3; ++i)
        #pragma unroll
        for (int j = 0; j < 3; ++j) {
            float ab = a1[i] * b1[j];
            #pragma unroll
            for (int k = 0; k < 5; ++k)
                o2[k] += w3s[70 + (i * 3 + j) * 5 + k] * ab;
        }

    g_xl[base] = o0;
    #pragma unroll
    for (int k = 0; k < 3; ++k) g_xl[base + (1 + k) * CDIM] = o1[k];
    #pragma unroll
    for (int k = 0; k < 5; ++k) g_xl[base + (4 + k) * CDIM] = o2[k];
}

// ---------------------------------------------------------------------------
extern "C" void kernel_launch(void* const* d_in, const int* in_sizes, int n_in,
                              void* d_out, int out_size) {
    const float* x  = (const float*)d_in[0];
    const float* Wl = (const float*)d_in[1];
    const float* bl = (const float*)d_in[2];
    const float* Wr = (const float*)d_in[3];
    const float* br = (const float*)d_in[4];
    const float* Wf = (const float*)d_in[5];
    const float* bf = (const float*)d_in[6];
    float* out = (float*)d_out;

    float *pxl = nullptr, *pxr = nullptr;
    cudaGetSymbolAddress((void**)&pxl, g_xl);
    cudaGetSymbolAddress((void**)&pxr, g_xr);

    const int LR_SMEM = 2 * IMG_B + 2 * WSET_B;  // 208896
    const int F_SMEM  = 2 * IMG_B + 1 * WSET_B;  // 139264
    cudaFuncSetAttribute(mma_gemm_kernel,
                         cudaFuncAttributeMaxDynamicSharedMemorySize, LR_SMEM);

    w3j_init_kernel<<<3, 128>>>();
    wsplit_kernel<<<9, 256>>>(Wl, Wr, Wf);

    dim3 grid(NTILES, MDIM);
    // left + right linears in one pass over x
    mma_gemm_kernel<<<grid, 256, LR_SMEM>>>(x, 0, 3, 2, bl, br, pxl, pxr);
    // CG tensor product
    tp_kernel<<<(NNODES * CDIM + 255) / 256, 256>>>();
    // final linear -> d_out
    mma_gemm_kernel<<<grid, 256, F_SMEM>>>(pxl, 6, 0, 1, bf, nullptr, out, nullptr);
}

// round 8
// speedup vs baseline: 5.6436x; 1.6263x over previous
#include <cuda_runtime.h>
#include <cuda_bf16.h>
#include <cstdint>

// Problem constants
#define NNODES  50000
#define CDIM    128
#define MDIM    9
#define CHUNK   64                                  // nodes per chunk
#define NCHUNKS ((NNODES + CHUNK - 1) / CHUNK)      // 782
#define GROUPS  16                                  // chunk-stride groups -> 16*9=144 CTAs
#define PITCH   136                                 // bf16 pitch; 272B rows, 16B aligned
#define WIMG_B  (128 * PITCH * 2)                   // 34816 B per 128x128 bf16 W image
#define WSET_B  (2 * WIMG_B)                        // hi+lo per weight set
#define AIMG_B  (CHUNK * PITCH * 2)                 // 17408 B per 64x128 bf16 A image
#define STG_B   (CHUNK * CDIM * 4)                  // 32768 B fp32 A stage

// ---------------------------------------------------------------------------
// Device scratch
// ---------------------------------------------------------------------------
__device__ float g_w3j[128];
__device__ __align__(16) char g_wimg[9 * WSET_B];
__device__ float g_xl[(size_t)NNODES * MDIM * CDIM];
__device__ float g_xr[(size_t)NNODES * MDIM * CDIM];

// ---------------------------------------------------------------------------
// HMMA + ldmatrix + cp.async helpers
// ---------------------------------------------------------------------------
__device__ __forceinline__ void mma_bf16(float* d, const uint32_t* a, uint32_t b0, uint32_t b1) {
    asm volatile(
        "mma.sync.aligned.m16n8k16.row.col.f32.bf16.bf16.f32 "
        "{%0,%1,%2,%3}, {%4,%5,%6,%7}, {%8,%9}, {%0,%1,%2,%3};"
        : "+f"(d[0]), "+f"(d[1]), "+f"(d[2]), "+f"(d[3])
        : "r"(a[0]), "r"(a[1]), "r"(a[2]), "r"(a[3]), "r"(b0), "r"(b1));
}
__device__ __forceinline__ void ldsm_x4(uint32_t& r0, uint32_t& r1, uint32_t& r2, uint32_t& r3,
                                        uint32_t addr) {
    asm volatile("ldmatrix.sync.aligned.m8n8.x4.shared.b16 {%0,%1,%2,%3}, [%4];"
                 : "=r"(r0), "=r"(r1), "=r"(r2), "=r"(r3) : "r"(addr));
}
__device__ __forceinline__ uint32_t smem_u32(const void* p) {
    return (uint32_t)__cvta_generic_to_shared(p);
}
__device__ __forceinline__ void cp_async16(uint32_t dst, const void* src, bool valid) {
    int sz = valid ? 16 : 0;
    asm volatile("cp.async.cg.shared.global [%0], [%1], 16, %2;"
                 :: "r"(dst), "l"(src), "r"(sz));
}
__device__ __forceinline__ void cp_commit() { asm volatile("cp.async.commit_group;"); }
__device__ __forceinline__ void cp_wait0()  { asm volatile("cp.async.wait_group 0;" ::: "memory"); }

// ---------------------------------------------------------------------------
// Wigner-3j init — parallel (3 blocks x 128 threads)
// ---------------------------------------------------------------------------
struct C2 { double r, i; };
__device__ __forceinline__ C2 cmul(C2 a, C2 b) { return { a.r*b.r - a.i*b.i, a.r*b.i + a.i*b.r }; }
__device__ double dfact(int n) { double r = 1.0; for (int i = 2; i <= n; ++i) r *= (double)i; return r; }

__device__ double su2cg(int j1, int m1, int j2, int m2, int j3, int m3) {
    if (m3 != m1 + m2) return 0.0;
    int vmin = -j1 + j2 + m3; if (-j1 + m1 > vmin) vmin = -j1 + m1; if (0 > vmin) vmin = 0;
    int vmax = j2 + j3 + m1; if (j3 - j1 + j2 < vmax) vmax = j3 - j1 + j2; if (j3 + m3 < vmax) vmax = j3 + m3;
    double pref = sqrt((double)(2*j3+1) * dfact(j3+j1-j2) * dfact(j3-j1+j2) * dfact(j1+j2-j3)
                       / dfact(j1+j2+j3+1)
                       * dfact(j3+m3) * dfact(j3-m3)
                       / (dfact(j1-m1) * dfact(j1+m1) * dfact(j2-m2) * dfact(j2+m2)));
    double s = 0.0;
    for (int v = vmin; v <= vmax; ++v) {
        double sign = ((v + j2 + m2) & 1) ? -1.0 : 1.0;
        s += sign / dfact(v) * dfact(j2+j3+m1-v) * dfact(j1-m1+v)
             / (dfact(j3-j1+j2-v) * dfact(j3+m3-v) * dfact(v+j1-j2-m3));
    }
    return pref * s;
}

__device__ void qmat(int l, C2 Q[5][5]) {
    for (int a = 0; a < 5; ++a) for (int b = 0; b < 5; ++b) Q[a][b] = {0.0, 0.0};
    const double is2 = 0.7071067811865475244;
    for (int m = -l; m < 0; ++m) {
        Q[l+m][l-m] = { is2, 0.0 };
        Q[l+m][l+m] = { 0.0, -is2 };
    }
    Q[l][l] = { 1.0, 0.0 };
    for (int m = 1; m <= l; ++m) {
        double s = (m & 1) ? -1.0 : 1.0;
        Q[l+m][l+m] = { s * is2, 0.0 };
        Q[l+m][l-m] = { 0.0, s * is2 };
    }
    C2 f = (l == 0) ? C2{1.0, 0.0} : (l == 1) ? C2{0.0, -1.0} : C2{-1.0, 0.0};
    for (int a = 0; a < 2*l+1; ++a) for (int b = 0; b < 2*l+1; ++b) Q[a][b] = cmul(Q[a][b], f);
}

__global__ void w3j_init_kernel() {
    __shared__ double cgs[125];
    __shared__ double crs[125];
    __shared__ double red[128];

    const int tid = threadIdx.x;
    const int blk = blockIdx.x;
    const int l1 = (blk == 0) ? 2 : 1;
    const int l2 = (blk == 2) ? 1 : 2;
    const int lo = blk == 0 ? 0 : (blk == 1 ? 1 : 2);
    const double alpha = (blk == 0) ? 1.0 : (blk == 1 ? 1.7320508075688772935 : 2.2360679774997896964);
    const int off = (blk == 0) ? 0 : (blk == 1 ? 25 : 70);
    const int d1 = 2*l1+1, d2 = 2*l2+1, d3 = 2*lo+1;
    const int nel = d1 * d2 * d3;

    if (tid < nel) {
        int i = tid / (d2 * d3), k = (tid / d3) % d2, n = tid % d3;
        cgs[tid] = su2cg(l1, i - l1, l2, k - l2, lo, n - lo);
    }
    __syncthreads();

    double cr = 0.0;
    if (tid < nel) {
        C2 Q1[5][5], Q2[5][5], Q3[5][5];
        qmat(l1, Q1); qmat(l2, Q2); qmat(lo, Q3);
        int a = tid / (d2 * d3), b = (tid / d3) % d2, c = tid % d3;
        C2 s = {0.0, 0.0};
        for (int i = 0; i < d1; ++i)
            for (int k = 0; k < d2; ++k) {
                C2 q12 = cmul(Q1[i][a], Q2[k][b]);
                for (int n = 0; n < d3; ++n) {
                    double cg = cgs[(i * d2 + k) * d3 + n];
                    if (cg == 0.0) continue;
                    C2 q3c = { Q3[n][c].r, -Q3[n][c].i };
                    C2 t = cmul(q12, q3c);
                    s.r += t.r * cg; s.i += t.i * cg;
                }
            }
        cr = s.r;
        crs[tid] = cr;
    }

    red[tid] = (tid < nel) ? cr * cr : 0.0;
    __syncthreads();
    for (int stride = 64; stride > 0; stride >>= 1) {
        if (tid < stride) red[tid] += red[tid + stride];
        __syncthreads();
    }
    double inv = alpha * rsqrt(red[0]);

    if (tid < nel) g_w3j[off + tid] = (float)(crs[tid] * inv);
    if (blk == 2 && tid >= 115 && tid < 128) g_w3j[tid] = 0.0f;
}

// ---------------------------------------------------------------------------
// Weight prep
// ---------------------------------------------------------------------------
__global__ void wsplit_kernel(const float* __restrict__ Wl,
                              const float* __restrict__ Wr,
                              const float* __restrict__ Wf) {
    int b = blockIdx.x;
    int which = b / 3, ll = b % 3;
    const float* W = (which == 0 ? Wl : which == 1 ? Wr : Wf) + ll * CDIM * CDIM;
    char* hi = g_wimg + (size_t)b * WSET_B;
    char* lo = hi + WIMG_B;
    for (int i = threadIdx.x; i < CDIM * CDIM; i += blockDim.x) {
        int cout = i >> 7, k = i & 127;
        float x = W[i];
        __nv_bfloat16 h = __float2bfloat16(x);
        __nv_bfloat16 lw = __float2bfloat16(x - __bfloat162float(h));
        int o = (cout * PITCH + k) * 2;
        *(__nv_bfloat16*)(hi + o) = h;
        *(__nv_bfloat16*)(lo + o) = lw;
    }
}

// ---------------------------------------------------------------------------
// Persistent HMMA GEMM kernel with cp.async chunk pipeline.
// Grid: (GROUPS, 9). Each CTA: fixed m, stages W once, loops node chunks.
// CTA tile per chunk: 64 nodes x 128 couts. 8 warps in 2x4.
// smem: W sets | A_hi | A_lo | fp32 stage
// ---------------------------------------------------------------------------
template <int NOUT>
__global__ __launch_bounds__(256, 1)
void mma_gemm_kernel(const float* __restrict__ src,
                     int wb0, int wb1,
                     const float* __restrict__ bias0,
                     const float* __restrict__ bias1,
                     float* __restrict__ out0,
                     float* __restrict__ out1)
{
    extern __shared__ __align__(16) char smem[];
    char* Wsm   = smem;
    char* A_hi  = smem + NOUT * WSET_B;
    char* A_lo  = A_hi + AIMG_B;
    float* stg  = (float*)(A_lo + AIMG_B);

    const int tid = threadIdx.x, wid = tid >> 5, lane = tid & 31;
    const int g = lane >> 2, t = lane & 3;
    const int m = blockIdx.y;
    const int l = (m >= 4) ? 2 : (m >= 1) ? 1 : 0;
    const int warpR = wid & 1, warpC = wid >> 1;   // 2 x 4 warps

    // --- Stage W images once ---
    {
        const float4* s0 = (const float4*)(g_wimg + (size_t)(wb0 + l) * WSET_B);
        float4* d0 = (float4*)Wsm;
        for (int i = tid; i < WSET_B / 16; i += 256) d0[i] = s0[i];
        if (NOUT == 2) {
            const float4* s1 = (const float4*)(g_wimg + (size_t)(wb1 + l) * WSET_B);
            float4* d1 = (float4*)(Wsm + WSET_B);
            for (int i = tid; i < WSET_B / 16; i += 256) d1[i] = s1[i];
        }
    }

    // --- per-lane ldmatrix offsets (bytes) ---
    const int jm = lane >> 3, rr = lane & 7;
    uint32_t aoff[2];
    #pragma unroll
    for (int mf = 0; mf < 2; ++mf) {
        int row = warpR * 32 + mf * 16 + ((jm & 1) << 3) + rr;
        aoff[mf] = (uint32_t)((row * PITCH + ((jm >> 1) << 3)) * 2);
    }
    uint32_t boff[2];
    #pragma unroll
    for (int cp = 0; cp < 2; ++cp) {
        int n = warpC * 32 + cp * 16 + ((jm >> 1) << 3) + rr;
        boff[cp] = (uint32_t)((n * PITCH + ((jm & 1) << 3)) * 2);
    }

    const uint32_t uA_hi = smem_u32(A_hi), uA_lo = smem_u32(A_lo), uW = smem_u32(Wsm);
    const uint32_t uStg  = smem_u32(stg);

    // cp.async issue helper for chunk c: 2048 16B lines, 8 per thread
    auto issue_chunk = [&](int c) {
        int n0 = c * CHUNK;
        #pragma unroll
        for (int it = 0; it < 8; ++it) {
            int idx = it * 256 + tid;
            int row = idx >> 5, c4 = (idx & 31) << 2;
            int n = n0 + row;
            cp_async16(uStg + (uint32_t)(row * CDIM + c4) * 4,
                       &src[((size_t)n * MDIM + m) * CDIM + c4],
                       n < NNODES);
        }
        cp_commit();
    };

    int c = blockIdx.x;
    if (c < NCHUNKS) issue_chunk(c);

    for (; c < NCHUNKS; c += GROUPS) {
        const int n0 = c * CHUNK;
        cp_wait0();
        __syncthreads();   // A(c) landed; previous mainloop done with images

        // --- convert fp32 stage -> bf16 hi/lo images ---
        #pragma unroll
        for (int it = 0; it < 8; ++it) {
            int idx = it * 256 + tid;
            int row = idx >> 5, c4 = (idx & 31) << 2;
            float4 v = *(float4*)&stg[row * CDIM + c4];
            __nv_bfloat162 h01 = __floats2bfloat162_rn(v.x, v.y);
            __nv_bfloat162 h23 = __floats2bfloat162_rn(v.z, v.w);
            __nv_bfloat162 l01 = __floats2bfloat162_rn(v.x - __bfloat162float(h01.x),
                                                       v.y - __bfloat162float(h01.y));
            __nv_bfloat162 l23 = __floats2bfloat162_rn(v.z - __bfloat162float(h23.x),
                                                       v.w - __bfloat162float(h23.y));
            int o = (row * PITCH + c4) * 2;
            *(uint2*)(A_hi + o) = make_uint2(*(uint32_t*)&h01, *(uint32_t*)&h23);
            *(uint2*)(A_lo + o) = make_uint2(*(uint32_t*)&l01, *(uint32_t*)&l23);
        }
        __syncthreads();   // images ready; stage free

        if (c + GROUPS < NCHUNKS) issue_chunk(c + GROUPS);

        // --- mainloop: 3-pass hi/lo split, NOUT outputs sharing A frags ---
        float acc[NOUT][2][4][4];
        #pragma unroll
        for (int o = 0; o < NOUT; ++o)
            #pragma unroll
            for (int mf = 0; mf < 2; ++mf)
                #pragma unroll
                for (int cf = 0; cf < 4; ++cf)
                    #pragma unroll
                    for (int q = 0; q < 4; ++q) acc[o][mf][cf][q] = 0.f;

        #pragma unroll
        for (int pass = 0; pass < 3; ++pass) {
            const uint32_t uA = (pass == 2) ? uA_lo : uA_hi;
            #pragma unroll
            for (int ks = 0; ks < 8; ++ks) {
                const uint32_t kofs = (uint32_t)(ks * 32);
                uint32_t a[2][4];
                ldsm_x4(a[0][0], a[0][1], a[0][2], a[0][3], uA + aoff[0] + kofs);
                ldsm_x4(a[1][0], a[1][1], a[1][2], a[1][3], uA + aoff[1] + kofs);
                #pragma unroll
                for (int o = 0; o < NOUT; ++o) {
                    const uint32_t uWp = uW + o * WSET_B + ((pass == 1) ? WIMG_B : 0);
                    #pragma unroll
                    for (int cp = 0; cp < 2; ++cp) {
                        uint32_t b0, b1, b2, b3;
                        ldsm_x4(b0, b1, b2, b3, uWp + boff[cp] + kofs);
                        mma_bf16(acc[o][0][2*cp],     a[0], b0, b1);
                        mma_bf16(acc[o][1][2*cp],     a[1], b0, b1);
                        mma_bf16(acc[o][0][2*cp + 1], a[0], b2, b3);
                        mma_bf16(acc[o][1][2*cp + 1], a[1], b2, b3);
                    }
                }
            }
        }

        // --- epilogue: bias (m==0) + scattered float2 stores ---
        #pragma unroll
        for (int o = 0; o < NOUT; ++o) {
            const float* bias = o ? bias1 : bias0;
            float* out = o ? out1 : out0;
            #pragma unroll
            for (int mf = 0; mf < 2; ++mf) {
                int r0 = n0 + warpR * 32 + mf * 16 + g;
                int r1 = r0 + 8;
                #pragma unroll
                for (int cf = 0; cf < 4; ++cf) {
                    int cb = warpC * 32 + cf * 8 + 2 * t;
                    float bx = 0.f, by = 0.f;
                    if (m == 0) { bx = bias[cb]; by = bias[cb + 1]; }
                    if (r0 < NNODES)
                        *(float2*)&out[((size_t)r0 * MDIM + m) * CDIM + cb] =
                            make_float2(acc[o][mf][cf][0] + bx, acc[o][mf][cf][1] + by);
                    if (r1 < NNODES)
                        *(float2*)&out[((size_t)r1 * MDIM + m) * CDIM + cb] =
                            make_float2(acc[o][mf][cf][2] + bx, acc[o][mf][cf][3] + by);
                }
            }
        }
    }
}

// ---------------------------------------------------------------------------
// Channel-wise CG tensor product (fp32, memory-bound): (g_xl, g_xr) -> g_xl
// ---------------------------------------------------------------------------
__global__ __launch_bounds__(256)
void tp_kernel() {
    __shared__ float w3s[128];
    if (threadIdx.x < 128) w3s[threadIdx.x] = g_w3j[threadIdx.x];
    __syncthreads();

    int p = blockIdx.x * 256 + threadIdx.x;
    if (p >= NNODES * CDIM) return;
    int node = p >> 7, c = p & 127;
    size_t base = (size_t)node * MDIM * CDIM + c;

    float a1[3], b1[3], a2[5], b2[5];
    #pragma unroll
    for (int i = 0; i < 3; ++i) { a1[i] = g_xl[base + (1 + i) * CDIM]; b1[i] = g_xr[base + (1 + i) * CDIM]; }
    #pragma unroll
    for (int i = 0; i < 5; ++i) { a2[i] = g_xl[base + (4 + i) * CDIM]; b2[i] = g_xr[base + (4 + i) * CDIM]; }

    float o0 = 0.f;
    #pragma unroll
    for (int i = 0; i < 5; ++i)
        #pragma unroll
        for (int j = 0; j < 5; ++j)
            o0 += w3s[i * 5 + j] * a2[i] * b2[j];

    float o1[3] = {0.f, 0.f, 0.f};
    #pragma unroll
    for (int i = 0; i < 3; ++i)
        #pragma unroll
        for (int j = 0; j < 5; ++j) {
            float ab = a1[i] * b2[j];
            #pragma unroll
            for (int k = 0; k < 3; ++k)
                o1[k] += w3s[25 + (i * 5 + j) * 3 + k] * ab;
        }

    float o2[5] = {0.f, 0.f, 0.f, 0.f, 0.f};
    #pragma unroll
    for (int i = 0; i < 3; ++i)
        #pragma unroll
        for (int j = 0; j < 3; ++j) {
            float ab = a1[i] * b1[j];
            #pragma unroll
            for (int k = 0; k < 5; ++k)
                o2[k] += w3s[70 + (i * 3 + j) * 5 + k] * ab;
        }

    g_xl[base] = o0;
    #pragma unroll
    for (int k = 0; k < 3; ++k) g_xl[base + (1 + k) * CDIM] = o1[k];
    #pragma unroll
    for (int k = 0; k < 5; ++k) g_xl[base + (4 + k) * CDIM] = o2[k];
}

// ---------------------------------------------------------------------------
extern "C" void kernel_launch(void* const* d_in, const int* in_sizes, int n_in,
                              void* d_out, int out_size) {
    const float* x  = (const float*)d_in[0];
    const float* Wl = (const float*)d_in[1];
    const float* bl = (const float*)d_in[2];
    const float* Wr = (const float*)d_in[3];
    const float* br = (const float*)d_in[4];
    const float* Wf = (const float*)d_in[5];
    const float* bf = (const float*)d_in[6];
    float* out = (float*)d_out;

    float *pxl = nullptr, *pxr = nullptr;
    cudaGetSymbolAddress((void**)&pxl, g_xl);
    cudaGetSymbolAddress((void**)&pxr, g_xr);

    const int LR_SMEM = 2 * WSET_B + 2 * AIMG_B + STG_B;  // 206848
    const int F_SMEM  = 1 * WSET_B + 2 * AIMG_B + STG_B;  // 137216
    cudaFuncSetAttribute(mma_gemm_kernel<2>,
                         cudaFuncAttributeMaxDynamicSharedMemorySize, LR_SMEM);
    cudaFuncSetAttribute(mma_gemm_kernel<1>,
                         cudaFuncAttributeMaxDynamicSharedMemorySize, F_SMEM);

    w3j_init_kernel<<<3, 128>>>();
    wsplit_kernel<<<9, 256>>>(Wl, Wr, Wf);

    dim3 grid(GROUPS, MDIM);   // 144 CTAs
    // left + right linears in one pass over x
    mma_gemm_kernel<2><<<grid, 256, LR_SMEM>>>(x, 0, 3, bl, br, pxl, pxr);
    // CG tensor product
    tp_kernel<<<(NNODES * CDIM + 255) / 256, 256>>>();
    // final linear -> d_out
    mma_gemm_kernel<1><<<grid, 256, F_SMEM>>>(pxl, 6, 0, bf, nullptr, out, nullptr);
}

// round 9
// speedup vs baseline: 7.8046x; 1.3829x over previous
#include <cuda_runtime.h>
#include <cuda_fp16.h>
#include <cstdint>

// Problem constants
#define NNODES  50000
#define CDIM    128
#define MDIM    9
#define CHUNK   64                                  // nodes per chunk
#define NCHUNKS ((NNODES + CHUNK - 1) / CHUNK)      // 782
#define GROUPS  16                                  // chunk-stride groups -> 16*9=144 CTAs
#define PITCH   136                                 // fp16 pitch; 272B rows, 16B aligned
#define WIMG_B  (128 * PITCH * 2)                   // 34816 B per 128x128 fp16 W image
#define WSET_B  (2 * WIMG_B)                        // hi+lo per weight set
#define AIMG_B  (CHUNK * PITCH * 2)                 // 17408 B per 64x128 fp16 A image
#define STG_B   (CHUNK * CDIM * 4)                  // 32768 B fp32 A stage

// ---------------------------------------------------------------------------
// Device scratch
// ---------------------------------------------------------------------------
__device__ float g_w3j[128];
__device__ __align__(16) char g_wimg[9 * WSET_B];
__device__ float g_xl[(size_t)NNODES * MDIM * CDIM];
__device__ float g_xr[(size_t)NNODES * MDIM * CDIM];

// ---------------------------------------------------------------------------
// HMMA + ldmatrix + cp.async helpers
// ---------------------------------------------------------------------------
__device__ __forceinline__ void mma_f16(float* d, const uint32_t* a, uint32_t b0, uint32_t b1) {
    asm volatile(
        "mma.sync.aligned.m16n8k16.row.col.f32.f16.f16.f32 "
        "{%0,%1,%2,%3}, {%4,%5,%6,%7}, {%8,%9}, {%0,%1,%2,%3};"
        : "+f"(d[0]), "+f"(d[1]), "+f"(d[2]), "+f"(d[3])
        : "r"(a[0]), "r"(a[1]), "r"(a[2]), "r"(a[3]), "r"(b0), "r"(b1));
}
__device__ __forceinline__ void ldsm_x4(uint32_t& r0, uint32_t& r1, uint32_t& r2, uint32_t& r3,
                                        uint32_t addr) {
    asm volatile("ldmatrix.sync.aligned.m8n8.x4.shared.b16 {%0,%1,%2,%3}, [%4];"
                 : "=r"(r0), "=r"(r1), "=r"(r2), "=r"(r3) : "r"(addr));
}
__device__ __forceinline__ uint32_t smem_u32(const void* p) {
    return (uint32_t)__cvta_generic_to_shared(p);
}
__device__ __forceinline__ void cp_async16(uint32_t dst, const void* src, bool valid) {
    int sz = valid ? 16 : 0;
    asm volatile("cp.async.cg.shared.global [%0], [%1], 16, %2;"
                 :: "r"(dst), "l"(src), "r"(sz));
}
__device__ __forceinline__ void cp_commit() { asm volatile("cp.async.commit_group;"); }
__device__ __forceinline__ void cp_wait0()  { asm volatile("cp.async.wait_group 0;" ::: "memory"); }

// ---------------------------------------------------------------------------
// Wigner-3j init — parallel (3 blocks x 128 threads)
// ---------------------------------------------------------------------------
struct C2 { double r, i; };
__device__ __forceinline__ C2 cmul(C2 a, C2 b) { return { a.r*b.r - a.i*b.i, a.r*b.i + a.i*b.r }; }
__device__ double dfact(int n) { double r = 1.0; for (int i = 2; i <= n; ++i) r *= (double)i; return r; }

__device__ double su2cg(int j1, int m1, int j2, int m2, int j3, int m3) {
    if (m3 != m1 + m2) return 0.0;
    int vmin = -j1 + j2 + m3; if (-j1 + m1 > vmin) vmin = -j1 + m1; if (0 > vmin) vmin = 0;
    int vmax = j2 + j3 + m1; if (j3 - j1 + j2 < vmax) vmax = j3 - j1 + j2; if (j3 + m3 < vmax) vmax = j3 + m3;
    double pref = sqrt((double)(2*j3+1) * dfact(j3+j1-j2) * dfact(j3-j1+j2) * dfact(j1+j2-j3)
                       / dfact(j1+j2+j3+1)
                       * dfact(j3+m3) * dfact(j3-m3)
                       / (dfact(j1-m1) * dfact(j1+m1) * dfact(j2-m2) * dfact(j2+m2)));
    double s = 0.0;
    for (int v = vmin; v <= vmax; ++v) {
        double sign = ((v + j2 + m2) & 1) ? -1.0 : 1.0;
        s += sign / dfact(v) * dfact(j2+j3+m1-v) * dfact(j1-m1+v)
             / (dfact(j3-j1+j2-v) * dfact(j3+m3-v) * dfact(v+j1-j2-m3));
    }
    return pref * s;
}

__device__ void qmat(int l, C2 Q[5][5]) {
    for (int a = 0; a < 5; ++a) for (int b = 0; b < 5; ++b) Q[a][b] = {0.0, 0.0};
    const double is2 = 0.7071067811865475244;
    for (int m = -l; m < 0; ++m) {
        Q[l+m][l-m] = { is2, 0.0 };
        Q[l+m][l+m] = { 0.0, -is2 };
    }
    Q[l][l] = { 1.0, 0.0 };
    for (int m = 1; m <= l; ++m) {
        double s = (m & 1) ? -1.0 : 1.0;
        Q[l+m][l+m] = { s * is2, 0.0 };
        Q[l+m][l-m] = { 0.0, s * is2 };
    }
    C2 f = (l == 0) ? C2{1.0, 0.0} : (l == 1) ? C2{0.0, -1.0} : C2{-1.0, 0.0};
    for (int a = 0; a < 2*l+1; ++a) for (int b = 0; b < 2*l+1; ++b) Q[a][b] = cmul(Q[a][b], f);
}

__global__ void w3j_init_kernel() {
    __shared__ double cgs[125];
    __shared__ double crs[125];
    __shared__ double red[128];

    const int tid = threadIdx.x;
    const int blk = blockIdx.x;
    const int l1 = (blk == 0) ? 2 : 1;
    const int l2 = (blk == 2) ? 1 : 2;
    const int lo = blk == 0 ? 0 : (blk == 1 ? 1 : 2);
    const double alpha = (blk == 0) ? 1.0 : (blk == 1 ? 1.7320508075688772935 : 2.2360679774997896964);
    const int off = (blk == 0) ? 0 : (blk == 1 ? 25 : 70);
    const int d1 = 2*l1+1, d2 = 2*l2+1, d3 = 2*lo+1;
    const int nel = d1 * d2 * d3;

    if (tid < nel) {
        int i = tid / (d2 * d3), k = (tid / d3) % d2, n = tid % d3;
        cgs[tid] = su2cg(l1, i - l1, l2, k - l2, lo, n - lo);
    }
    __syncthreads();

    double cr = 0.0;
    if (tid < nel) {
        C2 Q1[5][5], Q2[5][5], Q3[5][5];
        qmat(l1, Q1); qmat(l2, Q2); qmat(lo, Q3);
        int a = tid / (d2 * d3), b = (tid / d3) % d2, c = tid % d3;
        C2 s = {0.0, 0.0};
        for (int i = 0; i < d1; ++i)
            for (int k = 0; k < d2; ++k) {
                C2 q12 = cmul(Q1[i][a], Q2[k][b]);
                for (int n = 0; n < d3; ++n) {
                    double cg = cgs[(i * d2 + k) * d3 + n];
                    if (cg == 0.0) continue;
                    C2 q3c = { Q3[n][c].r, -Q3[n][c].i };
                    C2 t = cmul(q12, q3c);
                    s.r += t.r * cg; s.i += t.i * cg;
                }
            }
        cr = s.r;
        crs[tid] = cr;
    }

    red[tid] = (tid < nel) ? cr * cr : 0.0;
    __syncthreads();
    for (int stride = 64; stride > 0; stride >>= 1) {
        if (tid < stride) red[tid] += red[tid + stride];
        __syncthreads();
    }
    double inv = alpha * rsqrt(red[0]);

    if (tid < nel) g_w3j[off + tid] = (float)(crs[tid] * inv);
    if (blk == 2 && tid >= 115 && tid < 128) g_w3j[tid] = 0.0f;
}

// ---------------------------------------------------------------------------
// Weight prep: exact fp16 hi/lo split of W (lo captures the fp16 residual).
// ---------------------------------------------------------------------------
__global__ void wsplit_kernel(const float* __restrict__ Wl,
                              const float* __restrict__ Wr,
                              const float* __restrict__ Wf) {
    int b = blockIdx.x;
    int which = b / 3, ll = b % 3;
    const float* W = (which == 0 ? Wl : which == 1 ? Wr : Wf) + ll * CDIM * CDIM;
    char* hi = g_wimg + (size_t)b * WSET_B;
    char* lo = hi + WIMG_B;
    for (int i = threadIdx.x; i < CDIM * CDIM; i += blockDim.x) {
        int cout = i >> 7, k = i & 127;
        float x = W[i];
        __half h = __float2half_rn(x);
        __half lw = __float2half_rn(x - __half2float(h));
        int o = (cout * PITCH + k) * 2;
        *(__half*)(hi + o) = h;
        *(__half*)(lo + o) = lw;
    }
}

// ---------------------------------------------------------------------------
// Persistent HMMA GEMM kernel with cp.async chunk pipeline.
// A rounded once to fp16; W split hi+lo -> out = fp16(A) * W  (2 passes).
// Grid: (GROUPS, 9). CTA tile per chunk: 64 nodes x 128 couts, 8 warps (2x4).
// smem: W sets | A image | fp32 stage
// ---------------------------------------------------------------------------
template <int NOUT>
__global__ __launch_bounds__(256, 1)
void mma_gemm_kernel(const float* __restrict__ src,
                     int wb0, int wb1,
                     const float* __restrict__ bias0,
                     const float* __restrict__ bias1,
                     float* __restrict__ out0,
                     float* __restrict__ out1)
{
    extern __shared__ __align__(16) char smem[];
    char* Wsm   = smem;
    char* A_img = smem + NOUT * WSET_B;
    float* stg  = (float*)(A_img + AIMG_B);

    const int tid = threadIdx.x, wid = tid >> 5, lane = tid & 31;
    const int g = lane >> 2, t = lane & 3;
    const int m = blockIdx.y;
    const int l = (m >= 4) ? 2 : (m >= 1) ? 1 : 0;
    const int warpR = wid & 1, warpC = wid >> 1;   // 2 x 4 warps

    // --- Stage W images once ---
    {
        const float4* s0 = (const float4*)(g_wimg + (size_t)(wb0 + l) * WSET_B);
        float4* d0 = (float4*)Wsm;
        for (int i = tid; i < WSET_B / 16; i += 256) d0[i] = s0[i];
        if (NOUT == 2) {
            const float4* s1 = (const float4*)(g_wimg + (size_t)(wb1 + l) * WSET_B);
            float4* d1 = (float4*)(Wsm + WSET_B);
            for (int i = tid; i < WSET_B / 16; i += 256) d1[i] = s1[i];
        }
    }

    // --- per-lane ldmatrix offsets (bytes) ---
    const int jm = lane >> 3, rr = lane & 7;
    uint32_t aoff[2];
    #pragma unroll
    for (int mf = 0; mf < 2; ++mf) {
        int row = warpR * 32 + mf * 16 + ((jm & 1) << 3) + rr;
        aoff[mf] = (uint32_t)((row * PITCH + ((jm >> 1) << 3)) * 2);
    }
    uint32_t boff[2];
    #pragma unroll
    for (int cp = 0; cp < 2; ++cp) {
        int n = warpC * 32 + cp * 16 + ((jm >> 1) << 3) + rr;
        boff[cp] = (uint32_t)((n * PITCH + ((jm & 1) << 3)) * 2);
    }

    const uint32_t uA = smem_u32(A_img), uW = smem_u32(Wsm);
    const uint32_t uStg = smem_u32(stg);

    // cp.async issue helper for chunk c: 2048 16B lines, 8 per thread
    auto issue_chunk = [&](int c) {
        int n0 = c * CHUNK;
        #pragma unroll
        for (int it = 0; it < 8; ++it) {
            int idx = it * 256 + tid;
            int row = idx >> 5, c4 = (idx & 31) << 2;
            int n = n0 + row;
            cp_async16(uStg + (uint32_t)(row * CDIM + c4) * 4,
                       &src[((size_t)n * MDIM + m) * CDIM + c4],
                       n < NNODES);
        }
        cp_commit();
    };

    int c = blockIdx.x;
    if (c < NCHUNKS) issue_chunk(c);

    for (; c < NCHUNKS; c += GROUPS) {
        const int n0 = c * CHUNK;
        cp_wait0();
        __syncthreads();   // A(c) landed; previous mainloop done with image

        // --- convert fp32 stage -> fp16 image ---
        #pragma unroll
        for (int it = 0; it < 8; ++it) {
            int idx = it * 256 + tid;
            int row = idx >> 5, c4 = (idx & 31) << 2;
            float4 v = *(float4*)&stg[row * CDIM + c4];
            __half2 h01 = __floats2half2_rn(v.x, v.y);
            __half2 h23 = __floats2half2_rn(v.z, v.w);
            *(uint2*)(A_img + (row * PITCH + c4) * 2) =
                make_uint2(*(uint32_t*)&h01, *(uint32_t*)&h23);
        }
        __syncthreads();   // image ready; stage free

        if (c + GROUPS < NCHUNKS) issue_chunk(c + GROUPS);

        // --- mainloop: 2 passes (W_hi, W_lo), NOUT outputs sharing A frags ---
        float acc[NOUT][2][4][4];
        #pragma unroll
        for (int o = 0; o < NOUT; ++o)
            #pragma unroll
            for (int mf = 0; mf < 2; ++mf)
                #pragma unroll
                for (int cf = 0; cf < 4; ++cf)
                    #pragma unroll
                    for (int q = 0; q < 4; ++q) acc[o][mf][cf][q] = 0.f;

        #pragma unroll
        for (int ks = 0; ks < 8; ++ks) {
            const uint32_t kofs = (uint32_t)(ks * 32);
            uint32_t a[2][4];
            ldsm_x4(a[0][0], a[0][1], a[0][2], a[0][3], uA + aoff[0] + kofs);
            ldsm_x4(a[1][0], a[1][1], a[1][2], a[1][3], uA + aoff[1] + kofs);
            #pragma unroll
            for (int o = 0; o < NOUT; ++o) {
                #pragma unroll
                for (int pass = 0; pass < 2; ++pass) {
                    const uint32_t uWp = uW + o * WSET_B + pass * WIMG_B;
                    #pragma unroll
                    for (int cp = 0; cp < 2; ++cp) {
                        uint32_t b0, b1, b2, b3;
                        ldsm_x4(b0, b1, b2, b3, uWp + boff[cp] + kofs);
                        mma_f16(acc[o][0][2*cp],     a[0], b0, b1);
                        mma_f16(acc[o][1][2*cp],     a[1], b0, b1);
                        mma_f16(acc[o][0][2*cp + 1], a[0], b2, b3);
                        mma_f16(acc[o][1][2*cp + 1], a[1], b2, b3);
                    }
                }
            }
        }

        // --- epilogue: bias (m==0) + scattered float2 stores ---
        #pragma unroll
        for (int o = 0; o < NOUT; ++o) {
            const float* bias = o ? bias1 : bias0;
            float* out = o ? out1 : out0;
            #pragma unroll
            for (int mf = 0; mf < 2; ++mf) {
                int r0 = n0 + warpR * 32 + mf * 16 + g;
                int r1 = r0 + 8;
                #pragma unroll
                for (int cf = 0; cf < 4; ++cf) {
                    int cb = warpC * 32 + cf * 8 + 2 * t;
                    float bx = 0.f, by = 0.f;
                    if (m == 0) { bx = bias[cb]; by = bias[cb + 1]; }
                    if (r0 < NNODES)
                        *(float2*)&out[((size_t)r0 * MDIM + m) * CDIM + cb] =
                            make_float2(acc[o][mf][cf][0] + bx, acc[o][mf][cf][1] + by);
                    if (r1 < NNODES)
                        *(float2*)&out[((size_t)r1 * MDIM + m) * CDIM + cb] =
                            make_float2(acc[o][mf][cf][2] + bx, acc[o][mf][cf][3] + by);
                }
            }
        }
    }
}

// ---------------------------------------------------------------------------
// Channel-wise CG tensor product (fp32, memory-bound): (g_xl, g_xr) -> g_xl
// ---------------------------------------------------------------------------
__global__ __launch_bounds__(256)
void tp_kernel() {
    __shared__ float w3s[128];
    if (threadIdx.x < 128) w3s[threadIdx.x] = g_w3j[threadIdx.x];
    __syncthreads();

    int p = blockIdx.x * 256 + threadIdx.x;
    if (p >= NNODES * CDIM) return;
    int node = p >> 7, c = p & 127;
    size_t base = (size_t)node * MDIM * CDIM + c;

    float a1[3], b1[3], a2[5], b2[5];
    #pragma unroll
    for (int i = 0; i < 3; ++i) { a1[i] = g_xl[base + (1 + i) * CDIM]; b1[i] = g_xr[base + (1 + i) * CDIM]; }
    #pragma unroll
    for (int i = 0; i < 5; ++i) { a2[i] = g_xl[base + (4 + i) * CDIM]; b2[i] = g_xr[base + (4 + i) * CDIM]; }

    float o0 = 0.f;
    #pragma unroll
    for (int i = 0; i < 5; ++i)
        #pragma unroll
        for (int j = 0; j < 5; ++j)
            o0 += w3s[i * 5 + j] * a2[i] * b2[j];

    float o1[3] = {0.f, 0.f, 0.f};
    #pragma unroll
    for (int i = 0; i < 3; ++i)
        #pragma unroll
        for (int j = 0; j < 5; ++j) {
            float ab = a1[i] * b2[j];
            #pragma unroll
            for (int k = 0; k < 3; ++k)
                o1[k] += w3s[25 + (i * 5 + j) * 3 + k] * ab;
        }

    float o2[5] = {0.f, 0.f, 0.f, 0.f, 0.f};
    #pragma unroll
    for (int i = 0; i < 3; ++i)
        #pragma unroll
        for (int j = 0; j < 3; ++j) {
            float ab = a1[i] * b1[j];
            #pragma unroll
            for (int k = 0; k < 5; ++k)
                o2[k] += w3s[70 + (i * 3 + j) * 5 + k] * ab;
        }

    g_xl[base] = o0;
    #pragma unroll
    for (int k = 0; k < 3; ++k) g_xl[base + (1 + k) * CDIM] = o1[k];
    #pragma unroll
    for (int k = 0; k < 5; ++k) g_xl[base + (4 + k) * CDIM] = o2[k];
}

// ---------------------------------------------------------------------------
extern "C" void kernel_launch(void* const* d_in, const int* in_sizes, int n_in,
                              void* d_out, int out_size) {
    const float* x  = (const float*)d_in[0];
    const float* Wl = (const float*)d_in[1];
    const float* bl = (const float*)d_in[2];
    const float* Wr = (const float*)d_in[3];
    const float* br = (const float*)d_in[4];
    const float* Wf = (const float*)d_in[5];
    const float* bf = (const float*)d_in[6];
    float* out = (float*)d_out;

    float *pxl = nullptr, *pxr = nullptr;
    cudaGetSymbolAddress((void**)&pxl, g_xl);
    cudaGetSymbolAddress((void**)&pxr, g_xr);

    const int LR_SMEM = 2 * WSET_B + AIMG_B + STG_B;  // 189440
    const int F_SMEM  = 1 * WSET_B + AIMG_B + STG_B;  // 119808
    cudaFuncSetAttribute(mma_gemm_kernel<2>,
                         cudaFuncAttributeMaxDynamicSharedMemorySize, LR_SMEM);
    cudaFuncSetAttribute(mma_gemm_kernel<1>,
                         cudaFuncAttributeMaxDynamicSharedMemorySize, F_SMEM);

    w3j_init_kernel<<<3, 128>>>();
    wsplit_kernel<<<9, 256>>>(Wl, Wr, Wf);

    dim3 grid(GROUPS, MDIM);   // 144 CTAs
    // left + right linears in one pass over x
    mma_gemm_kernel<2><<<grid, 256, LR_SMEM>>>(x, 0, 3, bl, br, pxl, pxr);
    // CG tensor product
    tp_kernel<<<(NNODES * CDIM + 255) / 256, 256>>>();
    // final linear -> d_out
    mma_gemm_kernel<1><<<grid, 256, F_SMEM>>>(pxl, 6, 0, bf, nullptr, out, nullptr);
}

// round 10
// speedup vs baseline: 10.0992x; 1.2940x over previous
#include <cuda_runtime.h>
#include <cuda_fp16.h>
#include <cstdint>

// Problem constants
#define NNODES  50000
#define CDIM    128
#define MDIM    9
#define CHUNK   64                                  // nodes per chunk
#define NCHUNKS ((NNODES + CHUNK - 1) / CHUNK)      // 782
#define GROUPS  16                                  // chunk-stride groups -> 16*9=144 CTAs
#define PITCH   136                                 // fp16 pitch; 272B rows, 16B aligned
#define WIMG_B  (128 * PITCH * 2)                   // 34816 B per 128x128 fp16 W image
#define AIMG_B  (CHUNK * PITCH * 2)                 // 17408 B per 64x128 fp16 A image

// ---------------------------------------------------------------------------
// Device scratch (fp16 intermediates)
// ---------------------------------------------------------------------------
__device__ float g_w3j[128];
__device__ __align__(16) char g_wimg[9 * WIMG_B];
__device__ __half g_xl[(size_t)NNODES * MDIM * CDIM];
__device__ __half g_xr[(size_t)NNODES * MDIM * CDIM];

// ---------------------------------------------------------------------------
// HMMA + ldmatrix + cp.async helpers
// ---------------------------------------------------------------------------
__device__ __forceinline__ void mma_f16(float* d, const uint32_t* a, uint32_t b0, uint32_t b1) {
    asm volatile(
        "mma.sync.aligned.m16n8k16.row.col.f32.f16.f16.f32 "
        "{%0,%1,%2,%3}, {%4,%5,%6,%7}, {%8,%9}, {%0,%1,%2,%3};"
        : "+f"(d[0]), "+f"(d[1]), "+f"(d[2]), "+f"(d[3])
        : "r"(a[0]), "r"(a[1]), "r"(a[2]), "r"(a[3]), "r"(b0), "r"(b1));
}
__device__ __forceinline__ void ldsm_x4(uint32_t& r0, uint32_t& r1, uint32_t& r2, uint32_t& r3,
                                        uint32_t addr) {
    asm volatile("ldmatrix.sync.aligned.m8n8.x4.shared.b16 {%0,%1,%2,%3}, [%4];"
                 : "=r"(r0), "=r"(r1), "=r"(r2), "=r"(r3) : "r"(addr));
}
__device__ __forceinline__ uint32_t smem_u32(const void* p) {
    return (uint32_t)__cvta_generic_to_shared(p);
}
__device__ __forceinline__ void cp_async16(uint32_t dst, const void* src, bool valid) {
    int sz = valid ? 16 : 0;
    asm volatile("cp.async.cg.shared.global [%0], [%1], 16, %2;"
                 :: "r"(dst), "l"(src), "r"(sz));
}
__device__ __forceinline__ void cp_commit() { asm volatile("cp.async.commit_group;"); }
__device__ __forceinline__ void cp_wait0()  { asm volatile("cp.async.wait_group 0;" ::: "memory"); }

// ---------------------------------------------------------------------------
// Wigner-3j init — parallel (3 blocks x 128 threads)
// ---------------------------------------------------------------------------
struct C2 { double r, i; };
__device__ __forceinline__ C2 cmul(C2 a, C2 b) { return { a.r*b.r - a.i*b.i, a.r*b.i + a.i*b.r }; }
__device__ double dfact(int n) { double r = 1.0; for (int i = 2; i <= n; ++i) r *= (double)i; return r; }

__device__ double su2cg(int j1, int m1, int j2, int m2, int j3, int m3) {
    if (m3 != m1 + m2) return 0.0;
    int vmin = -j1 + j2 + m3; if (-j1 + m1 > vmin) vmin = -j1 + m1; if (0 > vmin) vmin = 0;
    int vmax = j2 + j3 + m1; if (j3 - j1 + j2 < vmax) vmax = j3 - j1 + j2; if (j3 + m3 < vmax) vmax = j3 + m3;
    double pref = sqrt((double)(2*j3+1) * dfact(j3+j1-j2) * dfact(j3-j1+j2) * dfact(j1+j2-j3)
                       / dfact(j1+j2+j3+1)
                       * dfact(j3+m3) * dfact(j3-m3)
                       / (dfact(j1-m1) * dfact(j1+m1) * dfact(j2-m2) * dfact(j2+m2)));
    double s = 0.0;
    for (int v = vmin; v <= vmax; ++v) {
        double sign = ((v + j2 + m2) & 1) ? -1.0 : 1.0;
        s += sign / dfact(v) * dfact(j2+j3+m1-v) * dfact(j1-m1+v)
             / (dfact(j3-j1+j2-v) * dfact(j3+m3-v) * dfact(v+j1-j2-m3));
    }
    return pref * s;
}

__device__ void qmat(int l, C2 Q[5][5]) {
    for (int a = 0; a < 5; ++a) for (int b = 0; b < 5; ++b) Q[a][b] = {0.0, 0.0};
    const double is2 = 0.7071067811865475244;
    for (int m = -l; m < 0; ++m) {
        Q[l+m][l-m] = { is2, 0.0 };
        Q[l+m][l+m] = { 0.0, -is2 };
    }
    Q[l][l] = { 1.0, 0.0 };
    for (int m = 1; m <= l; ++m) {
        double s = (m & 1) ? -1.0 : 1.0;
        Q[l+m][l+m] = { s * is2, 0.0 };
        Q[l+m][l-m] = { 0.0, s * is2 };
    }
    C2 f = (l == 0) ? C2{1.0, 0.0} : (l == 1) ? C2{0.0, -1.0} : C2{-1.0, 0.0};
    for (int a = 0; a < 2*l+1; ++a) for (int b = 0; b < 2*l+1; ++b) Q[a][b] = cmul(Q[a][b], f);
}

__global__ void w3j_init_kernel() {
    __shared__ double cgs[125];
    __shared__ double crs[125];
    __shared__ double red[128];

    const int tid = threadIdx.x;
    const int blk = blockIdx.x;
    const int l1 = (blk == 0) ? 2 : 1;
    const int l2 = (blk == 2) ? 1 : 2;
    const int lo = blk == 0 ? 0 : (blk == 1 ? 1 : 2);
    const double alpha = (blk == 0) ? 1.0 : (blk == 1 ? 1.7320508075688772935 : 2.2360679774997896964);
    const int off = (blk == 0) ? 0 : (blk == 1 ? 25 : 70);
    const int d1 = 2*l1+1, d2 = 2*l2+1, d3 = 2*lo+1;
    const int nel = d1 * d2 * d3;

    if (tid < nel) {
        int i = tid / (d2 * d3), k = (tid / d3) % d2, n = tid % d3;
        cgs[tid] = su2cg(l1, i - l1, l2, k - l2, lo, n - lo);
    }
    __syncthreads();

    double cr = 0.0;
    if (tid < nel) {
        C2 Q1[5][5], Q2[5][5], Q3[5][5];
        qmat(l1, Q1); qmat(l2, Q2); qmat(lo, Q3);
        int a = tid / (d2 * d3), b = (tid / d3) % d2, c = tid % d3;
        C2 s = {0.0, 0.0};
        for (int i = 0; i < d1; ++i)
            for (int k = 0; k < d2; ++k) {
                C2 q12 = cmul(Q1[i][a], Q2[k][b]);
                for (int n = 0; n < d3; ++n) {
                    double cg = cgs[(i * d2 + k) * d3 + n];
                    if (cg == 0.0) continue;
                    C2 q3c = { Q3[n][c].r, -Q3[n][c].i };
                    C2 t = cmul(q12, q3c);
                    s.r += t.r * cg; s.i += t.i * cg;
                }
            }
        cr = s.r;
        crs[tid] = cr;
    }

    red[tid] = (tid < nel) ? cr * cr : 0.0;
    __syncthreads();
    for (int stride = 64; stride > 0; stride >>= 1) {
        if (tid < stride) red[tid] += red[tid + stride];
        __syncthreads();
    }
    double inv = alpha * rsqrt(red[0]);

    if (tid < nel) g_w3j[off + tid] = (float)(crs[tid] * inv);
    if (blk == 2 && tid >= 115 && tid < 128) g_w3j[tid] = 0.0f;
}

// ---------------------------------------------------------------------------
// Weight prep: round fp32 W to fp16 image [cout][k], pitch PITCH.
// ---------------------------------------------------------------------------
__global__ void wsplit_kernel(const float* __restrict__ Wl,
                              const float* __restrict__ Wr,
                              const float* __restrict__ Wf) {
    int b = blockIdx.x;
    int which = b / 3, ll = b % 3;
    const float* W = (which == 0 ? Wl : which == 1 ? Wr : Wf) + ll * CDIM * CDIM;
    char* img = g_wimg + (size_t)b * WIMG_B;
    for (int i = threadIdx.x; i < CDIM * CDIM; i += blockDim.x) {
        int cout = i >> 7, k = i & 127;
        *(__half*)(img + (cout * PITCH + k) * 2) = __float2half_rn(W[i]);
    }
}

// ---------------------------------------------------------------------------
// Persistent HMMA GEMM kernel, single fp16 pass, cp.async chunk pipeline.
// IN16: src is fp16 (cp.async straight into pitched image via small stage copy)
// NOUT==2 -> fp16 outputs (xl, xr); NOUT==1 -> fp32 output (d_out).
// ---------------------------------------------------------------------------
template <int NOUT, bool IN16>
__global__ __launch_bounds__(256, 1)
void mma_gemm_kernel(const void* __restrict__ src_,
                     int wb0, int wb1,
                     const float* __restrict__ bias0,
                     const float* __restrict__ bias1,
                     void* __restrict__ out0_,
                     void* __restrict__ out1_)
{
    constexpr int STGB = IN16 ? (CHUNK * CDIM * 2) : (CHUNK * CDIM * 4);
    extern __shared__ __align__(16) char smem[];
    char* Wsm   = smem;
    char* A_img = smem + NOUT * WIMG_B;
    char* stg   = A_img + AIMG_B;

    const int tid = threadIdx.x, wid = tid >> 5, lane = tid & 31;
    const int g = lane >> 2, t = lane & 3;
    const int m = blockIdx.y;
    const int l = (m >= 4) ? 2 : (m >= 1) ? 1 : 0;
    const int warpR = wid & 1, warpC = wid >> 1;   // 2 x 4 warps

    // --- Stage W images once ---
    {
        const float4* s0 = (const float4*)(g_wimg + (size_t)(wb0 + l) * WIMG_B);
        float4* d0 = (float4*)Wsm;
        for (int i = tid; i < WIMG_B / 16; i += 256) d0[i] = s0[i];
        if (NOUT == 2) {
            const float4* s1 = (const float4*)(g_wimg + (size_t)(wb1 + l) * WIMG_B);
            float4* d1 = (float4*)(Wsm + WIMG_B);
            for (int i = tid; i < WIMG_B / 16; i += 256) d1[i] = s1[i];
        }
    }

    // --- per-lane ldmatrix offsets (bytes) ---
    const int jm = lane >> 3, rr = lane & 7;
    uint32_t aoff[2];
    #pragma unroll
    for (int mf = 0; mf < 2; ++mf) {
        int row = warpR * 32 + mf * 16 + ((jm & 1) << 3) + rr;
        aoff[mf] = (uint32_t)((row * PITCH + ((jm >> 1) << 3)) * 2);
    }
    uint32_t boff[2];
    #pragma unroll
    for (int cp = 0; cp < 2; ++cp) {
        int n = warpC * 32 + cp * 16 + ((jm >> 1) << 3) + rr;
        boff[cp] = (uint32_t)((n * PITCH + ((jm & 1) << 3)) * 2);
    }

    const uint32_t uA = smem_u32(A_img), uW = smem_u32(Wsm);
    const uint32_t uStg = smem_u32(stg);

    // cp.async issue for chunk c into the stage buffer
    auto issue_chunk = [&](int c) {
        int n0 = c * CHUNK;
        if (IN16) {
            const __half* src = (const __half*)src_;
            #pragma unroll
            for (int it = 0; it < 4; ++it) {
                int idx = it * 256 + tid;          // 1024 16B lines
                int row = idx >> 4, c8 = (idx & 15) << 3;
                int n = n0 + row;
                cp_async16(uStg + (uint32_t)idx * 16,
                           &src[((size_t)n * MDIM + m) * CDIM + c8],
                           n < NNODES);
            }
        } else {
            const float* src = (const float*)src_;
            #pragma unroll
            for (int it = 0; it < 8; ++it) {
                int idx = it * 256 + tid;          // 2048 16B lines
                int row = idx >> 5, c4 = (idx & 31) << 2;
                int n = n0 + row;
                cp_async16(uStg + (uint32_t)idx * 16,
                           &src[((size_t)n * MDIM + m) * CDIM + c4],
                           n < NNODES);
            }
        }
        cp_commit();
    };

    int c = blockIdx.x;
    if (c < NCHUNKS) issue_chunk(c);

    for (; c < NCHUNKS; c += GROUPS) {
        const int n0 = c * CHUNK;
        cp_wait0();
        __syncthreads();   // A(c) staged; previous mainloop done with image

        // --- move stage -> pitched fp16 image ---
        if (IN16) {
            #pragma unroll
            for (int it = 0; it < 4; ++it) {
                int idx = it * 256 + tid;
                int row = idx >> 4, c8 = (idx & 15) << 3;
                *(uint4*)(A_img + (row * PITCH + c8) * 2) = *(uint4*)(stg + idx * 16);
            }
        } else {
            #pragma unroll
            for (int it = 0; it < 8; ++it) {
                int idx = it * 256 + tid;
                int row = idx >> 5, c4 = (idx & 31) << 2;
                float4 v = *(float4*)(stg + idx * 16);
                __half2 h01 = __floats2half2_rn(v.x, v.y);
                __half2 h23 = __floats2half2_rn(v.z, v.w);
                *(uint2*)(A_img + (row * PITCH + c4) * 2) =
                    make_uint2(*(uint32_t*)&h01, *(uint32_t*)&h23);
            }
        }
        __syncthreads();   // image ready; stage free

        if (c + GROUPS < NCHUNKS) issue_chunk(c + GROUPS);

        // --- mainloop: single fp16 pass, NOUT outputs sharing A frags ---
        float acc[NOUT][2][4][4];
        #pragma unroll
        for (int o = 0; o < NOUT; ++o)
            #pragma unroll
            for (int mf = 0; mf < 2; ++mf)
                #pragma unroll
                for (int cf = 0; cf < 4; ++cf)
                    #pragma unroll
                    for (int q = 0; q < 4; ++q) acc[o][mf][cf][q] = 0.f;

        #pragma unroll
        for (int ks = 0; ks < 8; ++ks) {
            const uint32_t kofs = (uint32_t)(ks * 32);
            uint32_t a[2][4];
            ldsm_x4(a[0][0], a[0][1], a[0][2], a[0][3], uA + aoff[0] + kofs);
            ldsm_x4(a[1][0], a[1][1], a[1][2], a[1][3], uA + aoff[1] + kofs);
            #pragma unroll
            for (int o = 0; o < NOUT; ++o) {
                const uint32_t uWp = uW + o * WIMG_B;
                #pragma unroll
                for (int cp = 0; cp < 2; ++cp) {
                    uint32_t b0, b1, b2, b3;
                    ldsm_x4(b0, b1, b2, b3, uWp + boff[cp] + kofs);
                    mma_f16(acc[o][0][2*cp],     a[0], b0, b1);
                    mma_f16(acc[o][1][2*cp],     a[1], b0, b1);
                    mma_f16(acc[o][0][2*cp + 1], a[0], b2, b3);
                    mma_f16(acc[o][1][2*cp + 1], a[1], b2, b3);
                }
            }
        }

        // --- epilogue: bias (m==0) + stores ---
        #pragma unroll
        for (int o = 0; o < NOUT; ++o) {
            const float* bias = o ? bias1 : bias0;
            void* out_ = o ? out1_ : out0_;
            #pragma unroll
            for (int mf = 0; mf < 2; ++mf) {
                int r0 = n0 + warpR * 32 + mf * 16 + g;
                int r1 = r0 + 8;
                #pragma unroll
                for (int cf = 0; cf < 4; ++cf) {
                    int cb = warpC * 32 + cf * 8 + 2 * t;
                    float bx = 0.f, by = 0.f;
                    if (m == 0) { bx = bias[cb]; by = bias[cb + 1]; }
                    if (NOUT == 2) {
                        __half* out = (__half*)out_;
                        if (r0 < NNODES) {
                            __half2 h = __floats2half2_rn(acc[o][mf][cf][0] + bx,
                                                          acc[o][mf][cf][1] + by);
                            *(uint32_t*)&out[((size_t)r0 * MDIM + m) * CDIM + cb] = *(uint32_t*)&h;
                        }
                        if (r1 < NNODES) {
                            __half2 h = __floats2half2_rn(acc[o][mf][cf][2] + bx,
                                                          acc[o][mf][cf][3] + by);
                            *(uint32_t*)&out[((size_t)r1 * MDIM + m) * CDIM + cb] = *(uint32_t*)&h;
                        }
                    } else {
                        float* out = (float*)out_;
                        if (r0 < NNODES)
                            *(float2*)&out[((size_t)r0 * MDIM + m) * CDIM + cb] =
                                make_float2(acc[o][mf][cf][0] + bx, acc[o][mf][cf][1] + by);
                        if (r1 < NNODES)
                            *(float2*)&out[((size_t)r1 * MDIM + m) * CDIM + cb] =
                                make_float2(acc[o][mf][cf][2] + bx, acc[o][mf][cf][3] + by);
                    }
                }
            }
        }
    }
}

// ---------------------------------------------------------------------------
// Channel-wise CG tensor product (fp16 in / fp32 math / fp16 out): g_xl <- TP
// ---------------------------------------------------------------------------
__global__ __launch_bounds__(256)
void tp_kernel() {
    __shared__ float w3s[128];
    if (threadIdx.x < 128) w3s[threadIdx.x] = g_w3j[threadIdx.x];
    __syncthreads();

    int p = blockIdx.x * 256 + threadIdx.x;
    if (p >= NNODES * CDIM) return;
    int node = p >> 7, c = p & 127;
    size_t base = (size_t)node * MDIM * CDIM + c;

    float a1[3], b1[3], a2[5], b2[5];
    #pragma unroll
    for (int i = 0; i < 3; ++i) {
        a1[i] = __half2float(g_xl[base + (1 + i) * CDIM]);
        b1[i] = __half2float(g_xr[base + (1 + i) * CDIM]);
    }
    #pragma unroll
    for (int i = 0; i < 5; ++i) {
        a2[i] = __half2float(g_xl[base + (4 + i) * CDIM]);
        b2[i] = __half2float(g_xr[base + (4 + i) * CDIM]);
    }

    float o0 = 0.f;
    #pragma unroll
    for (int i = 0; i < 5; ++i)
        #pragma unroll
        for (int j = 0; j < 5; ++j)
            o0 += w3s[i * 5 + j] * a2[i] * b2[j];

    float o1[3] = {0.f, 0.f, 0.f};
    #pragma unroll
    for (int i = 0; i < 3; ++i)
        #pragma unroll
        for (int j = 0; j < 5; ++j) {
            float ab = a1[i] * b2[j];
            #pragma unroll
            for (int k = 0; k < 3; ++k)
                o1[k] += w3s[25 + (i * 5 + j) * 3 + k] * ab;
        }

    float o2[5] = {0.f, 0.f, 0.f, 0.f, 0.f};
    #pragma unroll
    for (int i = 0; i < 3; ++i)
        #pragma unroll
        for (int j = 0; j < 3; ++j) {
            float ab = a1[i] * b1[j];
            #pragma unroll
            for (int k = 0; k < 5; ++k)
                o2[k] += w3s[70 + (i * 3 + j) * 5 + k] * ab;
        }

    g_xl[base] = __float2half_rn(o0);
    #pragma unroll
    for (int k = 0; k < 3; ++k) g_xl[base + (1 + k) * CDIM] = __float2half_rn(o1[k]);
    #pragma unroll
    for (int k = 0; k < 5; ++k) g_xl[base + (4 + k) * CDIM] = __float2half_rn(o2[k]);
}

// ---------------------------------------------------------------------------
extern "C" void kernel_launch(void* const* d_in, const int* in_sizes, int n_in,
                              void* d_out, int out_size) {
    const float* x  = (const float*)d_in[0];
    const float* Wl = (const float*)d_in[1];
    const float* bl = (const float*)d_in[2];
    const float* Wr = (const float*)d_in[3];
    const float* br = (const float*)d_in[4];
    const float* Wf = (const float*)d_in[5];
    const float* bf = (const float*)d_in[6];
    float* out = (float*)d_out;

    __half *pxl = nullptr, *pxr = nullptr;
    cudaGetSymbolAddress((void**)&pxl, g_xl);
    cudaGetSymbolAddress((void**)&pxr, g_xr);

    const int LR_SMEM = 2 * WIMG_B + AIMG_B + CHUNK * CDIM * 4;  // 119808
    const int F_SMEM  = 1 * WIMG_B + AIMG_B + CHUNK * CDIM * 2;  // 68608
    cudaFuncSetAttribute(mma_gemm_kernel<2, false>,
                         cudaFuncAttributeMaxDynamicSharedMemorySize, LR_SMEM);
    cudaFuncSetAttribute(mma_gemm_kernel<1, true>,
                         cudaFuncAttributeMaxDynamicSharedMemorySize, F_SMEM);

    w3j_init_kernel<<<3, 128>>>();
    wsplit_kernel<<<9, 256>>>(Wl, Wr, Wf);

    dim3 grid(GROUPS, MDIM);   // 144 CTAs
    // left + right linears in one pass over x (fp16 outputs)
    mma_gemm_kernel<2, false><<<grid, 256, LR_SMEM>>>(x, 0, 3, bl, br, pxl, pxr);
    // CG tensor product (fp16 in/out)
    tp_kernel<<<(NNODES * CDIM + 255) / 256, 256>>>();
    // final linear (fp16 input) -> fp32 d_out
    mma_gemm_kernel<1, true><<<grid, 256, F_SMEM>>>(pxl, 6, 0, bf, nullptr, out, nullptr);
}

// round 11
// speedup vs baseline: 11.0131x; 1.0905x over previous
#include <cuda_runtime.h>
#include <cuda_fp16.h>
#include <cstdint>

// Problem constants
#define NNODES  50000
#define CDIM    128
#define MDIM    9
#define CHUNK   32                                  // nodes per chunk
#define NCHUNKS ((NNODES + CHUNK - 1) / CHUNK)      // 1563
#define GRP_LR  32                                  // 32*9 = 288 CTAs (2/SM)
#define GRP_F   64                                  // 64*9 = 576 CTAs (4/SM)
#define PITCH   136                                 // fp16 pitch; 272B rows
#define WIMG_B  (128 * PITCH * 2)                   // 34816 B per 128x128 fp16 W image
#define AIMG_B  (CHUNK * PITCH * 2)                 // 8704 B per 32x128 fp16 A image
#define STG_B   (CHUNK * CDIM * 4)                  // 16384 B fp32 A stage (LR only)

// ---------------------------------------------------------------------------
// Device scratch (fp16 intermediates)
// ---------------------------------------------------------------------------
__device__ float g_w3j[128];
__device__ __align__(16) char g_wimg[9 * WIMG_B];
__device__ __half g_xl[(size_t)NNODES * MDIM * CDIM];
__device__ __half g_xr[(size_t)NNODES * MDIM * CDIM];

// ---------------------------------------------------------------------------
// HMMA + ldmatrix + cp.async helpers
// ---------------------------------------------------------------------------
__device__ __forceinline__ void mma_f16(float* d, const uint32_t* a, uint32_t b0, uint32_t b1) {
    asm volatile(
        "mma.sync.aligned.m16n8k16.row.col.f32.f16.f16.f32 "
        "{%0,%1,%2,%3}, {%4,%5,%6,%7}, {%8,%9}, {%0,%1,%2,%3};"
        : "+f"(d[0]), "+f"(d[1]), "+f"(d[2]), "+f"(d[3])
        : "r"(a[0]), "r"(a[1]), "r"(a[2]), "r"(a[3]), "r"(b0), "r"(b1));
}
__device__ __forceinline__ void ldsm_x4(uint32_t& r0, uint32_t& r1, uint32_t& r2, uint32_t& r3,
                                        uint32_t addr) {
    asm volatile("ldmatrix.sync.aligned.m8n8.x4.shared.b16 {%0,%1,%2,%3}, [%4];"
                 : "=r"(r0), "=r"(r1), "=r"(r2), "=r"(r3) : "r"(addr));
}
__device__ __forceinline__ uint32_t smem_u32(const void* p) {
    return (uint32_t)__cvta_generic_to_shared(p);
}
__device__ __forceinline__ void cp_async16(uint32_t dst, const void* src, bool valid) {
    int sz = valid ? 16 : 0;
    asm volatile("cp.async.cg.shared.global [%0], [%1], 16, %2;"
                 :: "r"(dst), "l"(src), "r"(sz));
}
__device__ __forceinline__ void cp_commit() { asm volatile("cp.async.commit_group;"); }
__device__ __forceinline__ void cp_wait0()  { asm volatile("cp.async.wait_group 0;" ::: "memory"); }
__device__ __forceinline__ void cp_wait1()  { asm volatile("cp.async.wait_group 1;" ::: "memory"); }

// ---------------------------------------------------------------------------
// Wigner-3j init — parallel (3 blocks x 128 threads)
// ---------------------------------------------------------------------------
struct C2 { double r, i; };
__device__ __forceinline__ C2 cmul(C2 a, C2 b) { return { a.r*b.r - a.i*b.i, a.r*b.i + a.i*b.r }; }
__device__ double dfact(int n) { double r = 1.0; for (int i = 2; i <= n; ++i) r *= (double)i; return r; }

__device__ double su2cg(int j1, int m1, int j2, int m2, int j3, int m3) {
    if (m3 != m1 + m2) return 0.0;
    int vmin = -j1 + j2 + m3; if (-j1 + m1 > vmin) vmin = -j1 + m1; if (0 > vmin) vmin = 0;
    int vmax = j2 + j3 + m1; if (j3 - j1 + j2 < vmax) vmax = j3 - j1 + j2; if (j3 + m3 < vmax) vmax = j3 + m3;
    double pref = sqrt((double)(2*j3+1) * dfact(j3+j1-j2) * dfact(j3-j1+j2) * dfact(j1+j2-j3)
                       / dfact(j1+j2+j3+1)
                       * dfact(j3+m3) * dfact(j3-m3)
                       / (dfact(j1-m1) * dfact(j1+m1) * dfact(j2-m2) * dfact(j2+m2)));
    double s = 0.0;
    for (int v = vmin; v <= vmax; ++v) {
        double sign = ((v + j2 + m2) & 1) ? -1.0 : 1.0;
        s += sign / dfact(v) * dfact(j2+j3+m1-v) * dfact(j1-m1+v)
             / (dfact(j3-j1+j2-v) * dfact(j3+m3-v) * dfact(v+j1-j2-m3));
    }
    return pref * s;
}

__device__ void qmat(int l, C2 Q[5][5]) {
    for (int a = 0; a < 5; ++a) for (int b = 0; b < 5; ++b) Q[a][b] = {0.0, 0.0};
    const double is2 = 0.7071067811865475244;
    for (int m = -l; m < 0; ++m) {
        Q[l+m][l-m] = { is2, 0.0 };
        Q[l+m][l+m] = { 0.0, -is2 };
    }
    Q[l][l] = { 1.0, 0.0 };
    for (int m = 1; m <= l; ++m) {
        double s = (m & 1) ? -1.0 : 1.0;
        Q[l+m][l+m] = { s * is2, 0.0 };
        Q[l+m][l-m] = { 0.0, s * is2 };
    }
    C2 f = (l == 0) ? C2{1.0, 0.0} : (l == 1) ? C2{0.0, -1.0} : C2{-1.0, 0.0};
    for (int a = 0; a < 2*l+1; ++a) for (int b = 0; b < 2*l+1; ++b) Q[a][b] = cmul(Q[a][b], f);
}

__global__ void w3j_init_kernel() {
    __shared__ double cgs[125];
    __shared__ double crs[125];
    __shared__ double red[128];

    const int tid = threadIdx.x;
    const int blk = blockIdx.x;
    const int l1 = (blk == 0) ? 2 : 1;
    const int l2 = (blk == 2) ? 1 : 2;
    const int lo = blk == 0 ? 0 : (blk == 1 ? 1 : 2);
    const double alpha = (blk == 0) ? 1.0 : (blk == 1 ? 1.7320508075688772935 : 2.2360679774997896964);
    const int off = (blk == 0) ? 0 : (blk == 1 ? 25 : 70);
    const int d1 = 2*l1+1, d2 = 2*l2+1, d3 = 2*lo+1;
    const int nel = d1 * d2 * d3;

    if (tid < nel) {
        int i = tid / (d2 * d3), k = (tid / d3) % d2, n = tid % d3;
        cgs[tid] = su2cg(l1, i - l1, l2, k - l2, lo, n - lo);
    }
    __syncthreads();

    double cr = 0.0;
    if (tid < nel) {
        C2 Q1[5][5], Q2[5][5], Q3[5][5];
        qmat(l1, Q1); qmat(l2, Q2); qmat(lo, Q3);
        int a = tid / (d2 * d3), b = (tid / d3) % d2, c = tid % d3;
        C2 s = {0.0, 0.0};
        for (int i = 0; i < d1; ++i)
            for (int k = 0; k < d2; ++k) {
                C2 q12 = cmul(Q1[i][a], Q2[k][b]);
                for (int n = 0; n < d3; ++n) {
                    double cg = cgs[(i * d2 + k) * d3 + n];
                    if (cg == 0.0) continue;
                    C2 q3c = { Q3[n][c].r, -Q3[n][c].i };
                    C2 t = cmul(q12, q3c);
                    s.r += t.r * cg; s.i += t.i * cg;
                }
            }
        cr = s.r;
        crs[tid] = cr;
    }

    red[tid] = (tid < nel) ? cr * cr : 0.0;
    __syncthreads();
    for (int stride = 64; stride > 0; stride >>= 1) {
        if (tid < stride) red[tid] += red[tid + stride];
        __syncthreads();
    }
    double inv = alpha * rsqrt(red[0]);

    if (tid < nel) g_w3j[off + tid] = (float)(crs[tid] * inv);
    if (blk == 2 && tid >= 115 && tid < 128) g_w3j[tid] = 0.0f;
}

// ---------------------------------------------------------------------------
// Weight prep: round fp32 W to fp16 image [cout][k], pitch PITCH.
// ---------------------------------------------------------------------------
__global__ void wsplit_kernel(const float* __restrict__ Wl,
                              const float* __restrict__ Wr,
                              const float* __restrict__ Wf) {
    int b = blockIdx.x;
    int which = b / 3, ll = b % 3;
    const float* W = (which == 0 ? Wl : which == 1 ? Wr : Wf) + ll * CDIM * CDIM;
    char* img = g_wimg + (size_t)b * WIMG_B;
    for (int i = threadIdx.x; i < CDIM * CDIM; i += blockDim.x) {
        int cout = i >> 7, k = i & 127;
        *(__half*)(img + (cout * PITCH + k) * 2) = __float2half_rn(W[i]);
    }
}

// ---------------------------------------------------------------------------
// LR GEMM: fp32 in, 2 fp16 outputs. CHUNK=32, 2 CTAs/SM.
// smem: Wl|Wr images (34816 ea) | A image (8704) | fp32 stage (16384) = 94720
// ---------------------------------------------------------------------------
__global__ __launch_bounds__(256, 2)
void lr_gemm_kernel(const float* __restrict__ src,
                    const float* __restrict__ bias0,
                    const float* __restrict__ bias1,
                    __half* __restrict__ out0,
                    __half* __restrict__ out1)
{
    extern __shared__ __align__(16) char smem[];
    char* Wsm   = smem;
    char* A_img = smem + 2 * WIMG_B;
    char* stg   = A_img + AIMG_B;

    const int tid = threadIdx.x, wid = tid >> 5, lane = tid & 31;
    const int g = lane >> 2, t = lane & 3;
    const int m = blockIdx.y;
    const int l = (m >= 4) ? 2 : (m >= 1) ? 1 : 0;
    const int warpR = wid & 1, warpC = wid >> 1;   // 2 x 4 warps, tile 16 rows x 32 couts

    // Stage W images once (left = wb 0+l, right = wb 3+l)
    {
        const float4* s0 = (const float4*)(g_wimg + (size_t)l * WIMG_B);
        const float4* s1 = (const float4*)(g_wimg + (size_t)(3 + l) * WIMG_B);
        float4* d0 = (float4*)Wsm;
        float4* d1 = (float4*)(Wsm + WIMG_B);
        for (int i = tid; i < WIMG_B / 16; i += 256) { d0[i] = s0[i]; d1[i] = s1[i]; }
    }

    // per-lane ldmatrix offsets (bytes)
    const int jm = lane >> 3, rr = lane & 7;
    const uint32_t aoff = (uint32_t)(((warpR * 16 + ((jm & 1) << 3) + rr) * PITCH
                                      + ((jm >> 1) << 3)) * 2);
    uint32_t boff[2];
    #pragma unroll
    for (int cp = 0; cp < 2; ++cp) {
        int n = warpC * 32 + cp * 16 + ((jm >> 1) << 3) + rr;
        boff[cp] = (uint32_t)((n * PITCH + ((jm & 1) << 3)) * 2);
    }

    const uint32_t uA = smem_u32(A_img), uW = smem_u32(Wsm), uStg = smem_u32(stg);

    auto issue_chunk = [&](int c) {
        int n0 = c * CHUNK;
        #pragma unroll
        for (int it = 0; it < 4; ++it) {
            int idx = it * 256 + tid;              // 1024 16B lines
            int row = idx >> 5, c4 = (idx & 31) << 2;
            int n = n0 + row;
            cp_async16(uStg + (uint32_t)idx * 16,
                       &src[((size_t)n * MDIM + m) * CDIM + c4],
                       n < NNODES);
        }
        cp_commit();
    };

    int c = blockIdx.x;
    if (c < NCHUNKS) issue_chunk(c);

    for (; c < NCHUNKS; c += GRP_LR) {
        const int n0 = c * CHUNK;
        cp_wait0();
        __syncthreads();

        // convert fp32 stage -> fp16 image
        #pragma unroll
        for (int it = 0; it < 4; ++it) {
            int idx = it * 256 + tid;
            int row = idx >> 5, c4 = (idx & 31) << 2;
            float4 v = *(float4*)(stg + idx * 16);
            __half2 h01 = __floats2half2_rn(v.x, v.y);
            __half2 h23 = __floats2half2_rn(v.z, v.w);
            *(uint2*)(A_img + (row * PITCH + c4) * 2) =
                make_uint2(*(uint32_t*)&h01, *(uint32_t*)&h23);
        }
        __syncthreads();

        if (c + GRP_LR < NCHUNKS) issue_chunk(c + GRP_LR);

        // mainloop
        float acc[2][4][4];
        #pragma unroll
        for (int o = 0; o < 2; ++o)
            #pragma unroll
            for (int cf = 0; cf < 4; ++cf)
                #pragma unroll
                for (int q = 0; q < 4; ++q) acc[o][cf][q] = 0.f;

        #pragma unroll
        for (int ks = 0; ks < 8; ++ks) {
            const uint32_t kofs = (uint32_t)(ks * 32);
            uint32_t a[4];
            ldsm_x4(a[0], a[1], a[2], a[3], uA + aoff + kofs);
            #pragma unroll
            for (int o = 0; o < 2; ++o) {
                const uint32_t uWp = uW + o * WIMG_B;
                #pragma unroll
                for (int cp = 0; cp < 2; ++cp) {
                    uint32_t b0, b1, b2, b3;
                    ldsm_x4(b0, b1, b2, b3, uWp + boff[cp] + kofs);
                    mma_f16(acc[o][2*cp],     a, b0, b1);
                    mma_f16(acc[o][2*cp + 1], a, b2, b3);
                }
            }
        }

        // epilogue
        #pragma unroll
        for (int o = 0; o < 2; ++o) {
            const float* bias = o ? bias1 : bias0;
            __half* out = o ? out1 : out0;
            int r0 = n0 + warpR * 16 + g;
            int r1 = r0 + 8;
            #pragma unroll
            for (int cf = 0; cf < 4; ++cf) {
                int cb = warpC * 32 + cf * 8 + 2 * t;
                float bx = 0.f, by = 0.f;
                if (m == 0) { bx = bias[cb]; by = bias[cb + 1]; }
                if (r0 < NNODES) {
                    __half2 h = __floats2half2_rn(acc[o][cf][0] + bx, acc[o][cf][1] + by);
                    *(uint32_t*)&out[((size_t)r0 * MDIM + m) * CDIM + cb] = *(uint32_t*)&h;
                }
                if (r1 < NNODES) {
                    __half2 h = __floats2half2_rn(acc[o][cf][2] + bx, acc[o][cf][3] + by);
                    *(uint32_t*)&out[((size_t)r1 * MDIM + m) * CDIM + cb] = *(uint32_t*)&h;
                }
            }
        }
    }
}

// ---------------------------------------------------------------------------
// Final GEMM: fp16 in (direct cp.async into double-buffered pitched images),
// fp32 out. CHUNK=32, 4 CTAs/SM. smem: W (34816) | A0|A1 (8704 ea) = 52224
// ---------------------------------------------------------------------------
__global__ __launch_bounds__(256, 4)
void f_gemm_kernel(const __half* __restrict__ src,
                   const float* __restrict__ bias0,
                   float* __restrict__ out0)
{
    extern __shared__ __align__(16) char smem[];
    char* Wsm  = smem;
    char* Aimg[2] = { smem + WIMG_B, smem + WIMG_B + AIMG_B };

    const int tid = threadIdx.x, wid = tid >> 5, lane = tid & 31;
    const int g = lane >> 2, t = lane & 3;
    const int m = blockIdx.y;
    const int l = (m >= 4) ? 2 : (m >= 1) ? 1 : 0;
    const int warpR = wid & 1, warpC = wid >> 1;

    {
        const float4* s0 = (const float4*)(g_wimg + (size_t)(6 + l) * WIMG_B);
        float4* d0 = (float4*)Wsm;
        for (int i = tid; i < WIMG_B / 16; i += 256) d0[i] = s0[i];
    }

    const int jm = lane >> 3, rr = lane & 7;
    const uint32_t aoff = (uint32_t)(((warpR * 16 + ((jm & 1) << 3) + rr) * PITCH
                                      + ((jm >> 1) << 3)) * 2);
    uint32_t boff[2];
    #pragma unroll
    for (int cp = 0; cp < 2; ++cp) {
        int n = warpC * 32 + cp * 16 + ((jm >> 1) << 3) + rr;
        boff[cp] = (uint32_t)((n * PITCH + ((jm & 1) << 3)) * 2);
    }
    const uint32_t uW = smem_u32(Wsm);
    const uint32_t uAimg[2] = { smem_u32(Aimg[0]), smem_u32(Aimg[1]) };

    // direct cp.async into pitched image (rows are 256B contiguous in gmem)
    auto issue_chunk = [&](int c, int buf) {
        int n0 = c * CHUNK;
        #pragma unroll
        for (int it = 0; it < 2; ++it) {
            int idx = it * 256 + tid;              // 512 16B lines
            int row = idx >> 4, c8 = (idx & 15) << 3;
            int n = n0 + row;
            cp_async16(uAimg[buf] + (uint32_t)(row * PITCH + c8) * 2,
                       &src[((size_t)n * MDIM + m) * CDIM + c8],
                       n < NNODES);
        }
        cp_commit();
    };

    int c = blockIdx.x;
    int buf = 0;
    if (c < NCHUNKS) issue_chunk(c, 0);

    for (; c < NCHUNKS; c += GRP_F) {
        const int n0 = c * CHUNK;
        bool more = (c + GRP_F < NCHUNKS);
        if (more) issue_chunk(c + GRP_F, buf ^ 1);
        if (more) cp_wait1(); else cp_wait0();
        __syncthreads();                            // A(c) visible to all

        const uint32_t uA = uAimg[buf];
        float acc[4][4];
        #pragma unroll
        for (int cf = 0; cf < 4; ++cf)
            #pragma unroll
            for (int q = 0; q < 4; ++q) acc[cf][q] = 0.f;

        #pragma unroll
        for (int ks = 0; ks < 8; ++ks) {
            const uint32_t kofs = (uint32_t)(ks * 32);
            uint32_t a[4];
            ldsm_x4(a[0], a[1], a[2], a[3], uA + aoff + kofs);
            #pragma unroll
            for (int cp = 0; cp < 2; ++cp) {
                uint32_t b0, b1, b2, b3;
                ldsm_x4(b0, b1, b2, b3, uW + boff[cp] + kofs);
                mma_f16(acc[2*cp],     a, b0, b1);
                mma_f16(acc[2*cp + 1], a, b2, b3);
            }
        }

        {
            int r0 = n0 + warpR * 16 + g;
            int r1 = r0 + 8;
            #pragma unroll
            for (int cf = 0; cf < 4; ++cf) {
                int cb = warpC * 32 + cf * 8 + 2 * t;
                float bx = 0.f, by = 0.f;
                if (m == 0) { bx = bias0[cb]; by = bias0[cb + 1]; }
                if (r0 < NNODES)
                    *(float2*)&out0[((size_t)r0 * MDIM + m) * CDIM + cb] =
                        make_float2(acc[cf][0] + bx, acc[cf][1] + by);
                if (r1 < NNODES)
                    *(float2*)&out0[((size_t)r1 * MDIM + m) * CDIM + cb] =
                        make_float2(acc[cf][2] + bx, acc[cf][3] + by);
            }
        }
        __syncthreads();                            // mainloop done before buf^1 refill next iter
        buf ^= 1;
    }
}

// ---------------------------------------------------------------------------
// Channel-wise CG tensor product, 2 channels/thread via __half2.
// ---------------------------------------------------------------------------
__global__ __launch_bounds__(256)
void tp_kernel() {
    __shared__ float w3s[128];
    if (threadIdx.x < 128) w3s[threadIdx.x] = g_w3j[threadIdx.x];
    __syncthreads();

    int p = blockIdx.x * 256 + threadIdx.x;
    if (p >= NNODES * (CDIM / 2)) return;
    int node = p >> 6, c2 = p & 63;
    const __half2* XL = (const __half2*)g_xl;
    const __half2* XR = (const __half2*)g_xr;
    __half2* OUT = (__half2*)g_xl;
    size_t base = (size_t)node * (MDIM * CDIM / 2) + c2;

    float2 a1[3], b1[3], a2[5], b2[5];
    #pragma unroll
    for (int i = 0; i < 3; ++i) {
        a1[i] = __half22float2(XL[base + (1 + i) * 64]);
        b1[i] = __half22float2(XR[base + (1 + i) * 64]);
    }
    #pragma unroll
    for (int i = 0; i < 5; ++i) {
        a2[i] = __half22float2(XL[base + (4 + i) * 64]);
        b2[i] = __half22float2(XR[base + (4 + i) * 64]);
    }

    float2 o0 = make_float2(0.f, 0.f);
    #pragma unroll
    for (int i = 0; i < 5; ++i)
        #pragma unroll
        for (int j = 0; j < 5; ++j) {
            float w = w3s[i * 5 + j];
            o0.x += w * a2[i].x * b2[j].x;
            o0.y += w * a2[i].y * b2[j].y;
        }

    float2 o1[3] = { {0.f,0.f}, {0.f,0.f}, {0.f,0.f} };
    #pragma unroll
    for (int i = 0; i < 3; ++i)
        #pragma unroll
        for (int j = 0; j < 5; ++j) {
            float abx = a1[i].x * b2[j].x;
            float aby = a1[i].y * b2[j].y;
            #pragma unroll
            for (int k = 0; k < 3; ++k) {
                float w = w3s[25 + (i * 5 + j) * 3 + k];
                o1[k].x += w * abx;
                o1[k].y += w * aby;
            }
        }

    float2 o2[5] = { {0.f,0.f}, {0.f,0.f}, {0.f,0.f}, {0.f,0.f}, {0.f,0.f} };
    #pragma unroll
    for (int i = 0; i < 3; ++i)
        #pragma unroll
        for (int j = 0; j < 3; ++j) {
            float abx = a1[i].x * b1[j].x;
            float aby = a1[i].y * b1[j].y;
            #pragma unroll
            for (int k = 0; k < 5; ++k) {
                float w = w3s[70 + (i * 3 + j) * 5 + k];
                o2[k].x += w * abx;
                o2[k].y += w * aby;
            }
        }

    OUT[base] = __floats2half2_rn(o0.x, o0.y);
    #pragma unroll
    for (int k = 0; k < 3; ++k) OUT[base + (1 + k) * 64] = __floats2half2_rn(o1[k].x, o1[k].y);
    #pragma unroll
    for (int k = 0; k < 5; ++k) OUT[base + (4 + k) * 64] = __floats2half2_rn(o2[k].x, o2[k].y);
}

// ---------------------------------------------------------------------------
extern "C" void kernel_launch(void* const* d_in, const int* in_sizes, int n_in,
                              void* d_out, int out_size) {
    const float* x  = (const float*)d_in[0];
    const float* Wl = (const float*)d_in[1];
    const float* bl = (const float*)d_in[2];
    const float* Wr = (const float*)d_in[3];
    const float* br = (const float*)d_in[4];
    const float* Wf = (const float*)d_in[5];
    const float* bf = (const float*)d_in[6];
    float* out = (float*)d_out;

    __half *pxl = nullptr, *pxr = nullptr;
    cudaGetSymbolAddress((void**)&pxl, g_xl);
    cudaGetSymbolAddress((void**)&pxr, g_xr);

    const int LR_SMEM = 2 * WIMG_B + AIMG_B + STG_B;   // 94720  -> 2 CTAs/SM
    const int F_SMEM  = WIMG_B + 2 * AIMG_B;           // 52224  -> 4 CTAs/SM
    cudaFuncSetAttribute(lr_gemm_kernel,
                         cudaFuncAttributeMaxDynamicSharedMemorySize, LR_SMEM);
    cudaFuncSetAttribute(f_gemm_kernel,
                         cudaFuncAttributeMaxDynamicSharedMemorySize, F_SMEM);

    w3j_init_kernel<<<3, 128>>>();
    wsplit_kernel<<<9, 256>>>(Wl, Wr, Wf);

    // left + right linears in one pass over x (fp16 outputs)
    lr_gemm_kernel<<<dim3(GRP_LR, MDIM), 256, LR_SMEM>>>(x, bl, br, pxl, pxr);
    // CG tensor product (fp16 in/out, 2 ch/thread)
    tp_kernel<<<(NNODES * (CDIM / 2) + 255) / 256, 256>>>();
    // final linear (fp16 input) -> fp32 d_out
    f_gemm_kernel<<<dim3(GRP_F, MDIM), 256, F_SMEM>>>(pxl, bf, out);
}